// round 2
// baseline (speedup 1.0000x reference)
#include <cuda_runtime.h>
#include <math.h>

#define Nn   16
#define Cc   256
#define C1c  128
#define C4c  64
#define Hh   56
#define Wc   56
#define HWc  3136
#define Pc   (Nn*HWc)
#define EPSf 1e-5f

// ---------------- scratch (device globals; no allocations) ----------------
__device__ float g_y  [Nn*Cc *HWc];   // gelu(bn(mlp)) ; ch 0..127 include +pos_h
__device__ float g_cat[Nn*C1c*HWc];   // [xh(64), xw(64)]
__device__ float g_t1 [Nn*C1c*HWc];   // after fuse_h + gelu(bn) + pos_w
__device__ float g_u1 [Nn*C1c*HWc];   // after fuse_w
__device__ float g_x2h[Nn*C1c*HWc];
__device__ float g_x2w[Nn*C1c*HWc];
__device__ float g_x2n[Nn*C1c*HWc];   // recombined x2
__device__ float g_att[Nn*C1c];
__device__ float g_a  [Nn*C1c*3];

__device__ __forceinline__ float gelu_f(float x) {
    return 0.5f * x * (1.0f + erff(x * 0.7071067811865476f));
}

// packed f32x2 helpers (FFMA2 path: 2x fp32 throughput on sm_103a)
__device__ __forceinline__ unsigned long long pk2(float lo, float hi) {
    unsigned long long r;
    asm("mov.b64 %0, {%1, %2};" : "=l"(r) : "f"(lo), "f"(hi));
    return r;
}
__device__ __forceinline__ void fma2(unsigned long long& d, unsigned long long a, unsigned long long b) {
    asm("fma.rn.f32x2 %0, %1, %2, %0;" : "+l"(d) : "l"(a), "l"(b));
}
__device__ __forceinline__ float2 upk2(unsigned long long v) {
    float2 r;
    asm("mov.b64 {%0, %1}, %2;" : "=f"(r.x), "=f"(r.y) : "l"(v));
    return r;
}

// ---------------------------------------------------------------------------
// Generic pointwise GEMM over pixels: out[o,q] = sum_c W[o*Cin+c] * in[c,q]
// in = channel-concat of (inA: cinA channels) then (inB: Cin-cinA channels),
// each stored NCHW with given per-image stride.
// Block tile 128 outputs x 128 pixels, 256 threads, 8x8 micro-tile, K-chunk 16,
// double-buffered smem, packed f32x2 accumulation.
// EPI: 0 none; 1 (+bias,BN,gelu,+pos if o<128); 2 (BN,gelu,+pos)
// ---------------------------------------------------------------------------
template<int EPI>
__global__ __launch_bounds__(256, 2)
void gemm_k(const float* __restrict__ Wm, int Cin,
            const float* __restrict__ inA, int cinA, int strA,
            const float* __restrict__ inB, int strB,
            float* __restrict__ out, int strO,
            const float* __restrict__ e_bias,
            const float* __restrict__ e_g, const float* __restrict__ e_b,
            const float* __restrict__ e_m, const float* __restrict__ e_v,
            const float* __restrict__ e_pos)
{
    __shared__ float Ws[2][16][132];
    __shared__ float Bs[2][16][132];

    const int tid = threadIdx.x;
    const int tx = tid & 15, ty = tid >> 4;
    const int q0 = blockIdx.x * 128;
    const int o0 = blockIdx.y * 128;

    // B-tile slot geometry (2 float4 slots per thread, fixed pixel position)
    int skk0, skk1, sn0, sn1, shw0, shw1, sp40, sp41;
    {
        int s = tid;          skk0 = s >> 5; sp40 = (s & 31) << 2;
        int q = q0 + sp40;    sn0 = q / HWc; shw0 = q - sn0 * HWc;
        s = tid + 256;        skk1 = s >> 5; sp41 = (s & 31) << 2;
        q = q0 + sp41;        sn1 = q / HWc; shw1 = q - sn1 * HWc;
    }
    // A-tile slot geometry
    const int aoo0 = tid >> 2,         akk0 = (tid & 3) << 2;
    const int aoo1 = (tid + 256) >> 2, akk1 = (tid & 3) << 2;

    unsigned long long acc[8][4];
#pragma unroll
    for (int i = 0; i < 8; i++)
#pragma unroll
        for (int j = 0; j < 4; j++) acc[i][j] = 0ull;

    const int nk = Cin >> 4;
    float4 ra0, ra1, rb0, rb1;

#define GEMM_FETCH(K0)                                                                   \
    do {                                                                                 \
        ra0 = *reinterpret_cast<const float4*>(&Wm[(long)(o0 + aoo0) * Cin + (K0) + akk0]); \
        ra1 = *reinterpret_cast<const float4*>(&Wm[(long)(o0 + aoo1) * Cin + (K0) + akk1]); \
        {                                                                                \
            int c = (K0) + skk0;                                                         \
            const float* p = (c < cinA)                                                  \
                ? inA + (long)sn0 * strA + (long)c * HWc + shw0                          \
                : inB + (long)sn0 * strB + (long)(c - cinA) * HWc + shw0;                \
            rb0 = *reinterpret_cast<const float4*>(p);                                   \
        }                                                                                \
        {                                                                                \
            int c = (K0) + skk1;                                                         \
            const float* p = (c < cinA)                                                  \
                ? inA + (long)sn1 * strA + (long)c * HWc + shw1                          \
                : inB + (long)sn1 * strB + (long)(c - cinA) * HWc + shw1;                \
            rb1 = *reinterpret_cast<const float4*>(p);                                   \
        }                                                                                \
    } while (0)

#define GEMM_STASH(BUF)                                                                  \
    do {                                                                                 \
        Ws[BUF][akk0 + 0][aoo0] = ra0.x; Ws[BUF][akk0 + 1][aoo0] = ra0.y;                \
        Ws[BUF][akk0 + 2][aoo0] = ra0.z; Ws[BUF][akk0 + 3][aoo0] = ra0.w;                \
        Ws[BUF][akk1 + 0][aoo1] = ra1.x; Ws[BUF][akk1 + 1][aoo1] = ra1.y;                \
        Ws[BUF][akk1 + 2][aoo1] = ra1.z; Ws[BUF][akk1 + 3][aoo1] = ra1.w;                \
        *reinterpret_cast<float4*>(&Bs[BUF][skk0][sp40]) = rb0;                          \
        *reinterpret_cast<float4*>(&Bs[BUF][skk1][sp41]) = rb1;                          \
    } while (0)

    GEMM_FETCH(0);
    GEMM_STASH(0);
    __syncthreads();

    for (int kc = 0; kc < nk; kc++) {
        const int cur = kc & 1;
        if (kc + 1 < nk) GEMM_FETCH((kc + 1) << 4);

#pragma unroll
        for (int kk = 0; kk < 16; kk++) {
            const float4 a0 = *reinterpret_cast<const float4*>(&Ws[cur][kk][ty << 2]);
            const float4 a1 = *reinterpret_cast<const float4*>(&Ws[cur][kk][64 + (ty << 2)]);
            const float4 b0 = *reinterpret_cast<const float4*>(&Bs[cur][kk][tx << 2]);
            const float4 b1 = *reinterpret_cast<const float4*>(&Bs[cur][kk][64 + (tx << 2)]);
            const unsigned long long bp0 = pk2(b0.x, b0.y), bp1 = pk2(b0.z, b0.w);
            const unsigned long long bp2 = pk2(b1.x, b1.y), bp3 = pk2(b1.z, b1.w);
            const float av[8] = {a0.x, a0.y, a0.z, a0.w, a1.x, a1.y, a1.z, a1.w};
#pragma unroll
            for (int i = 0; i < 8; i++) {
                const unsigned long long ap = pk2(av[i], av[i]);
                fma2(acc[i][0], ap, bp0);
                fma2(acc[i][1], ap, bp1);
                fma2(acc[i][2], ap, bp2);
                fma2(acc[i][3], ap, bp3);
            }
        }
        if (kc + 1 < nk) GEMM_STASH(cur ^ 1);
        __syncthreads();
    }

    // ------------------------- epilogue -------------------------
#pragma unroll
    for (int jg = 0; jg < 2; jg++) {
        const int col0 = jg * 64 + (tx << 2);
        const int q = q0 + col0;
        const int n = q / HWc;
        const int hw = q - n * HWc;
        int rel[4];
#pragma unroll
        for (int j = 0; j < 4; j++) {
            const int hwj = hw + j;
            const int h = hwj / 56;
            rel[j] = (hwj - h * 56) - h + 56;
        }
#pragma unroll
        for (int i = 0; i < 8; i++) {
            const int o = o0 + ((i < 4) ? ((ty << 2) + i) : (64 + (ty << 2) + i - 4));
            const float2 v01 = upk2(acc[i][jg * 2]);
            const float2 v23 = upk2(acc[i][jg * 2 + 1]);
            float v[4] = {v01.x, v01.y, v23.x, v23.y};
            if (EPI == 1) {
                const float s = e_g[o] * rsqrtf(e_v[o] + EPSf);
                const float t = e_b[o] - e_m[o] * s;
                const float bb = e_bias[o];
#pragma unroll
                for (int j = 0; j < 4; j++) {
                    float u = gelu_f((v[j] + bb) * s + t);
                    if (o < 128) u += __ldg(&e_pos[rel[j] * 128 + o]);
                    v[j] = u;
                }
            } else if (EPI == 2) {
                const float s = e_g[o] * rsqrtf(e_v[o] + EPSf);
                const float t = e_b[o] - e_m[o] * s;
#pragma unroll
                for (int j = 0; j < 4; j++) {
                    v[j] = gelu_f(v[j] * s + t) + __ldg(&e_pos[rel[j] * 128 + o]);
                }
            }
            float4 vv;
            vv.x = v[0]; vv.y = v[1]; vv.z = v[2]; vv.w = v[3];
            *reinterpret_cast<float4*>(&out[(long)n * strO + (long)o * HWc + hw]) = vv;
        }
    }
#undef GEMM_FETCH
#undef GEMM_STASH
}

// ---------------------------------------------------------------------------
// Strip conv. H-variant: xh[n,c,o,w] = b[c*56+o] + sum_{h',kw} W[(c*56+o)*168+h'*3+kw]*x1[n,c,h',w+kw-1]
// W-variant: xw[n,c,h,wo] = b[c*56+wo] + sum_{w',kh} W[(c*56+wo)*168+w'*3+kh]*x1[n,64+c,h+kh-1,w']
// Block = (c, n), 224 threads: tid>>2 selects o/wo in [0,56), tid&3 selects a
// 14-wide output strip. x1 plane staged in padded smem.
// ---------------------------------------------------------------------------
template<bool WVAR>
__global__ __launch_bounds__(224)
void strip_k(const float* __restrict__ Wg, const float* __restrict__ bias)
{
    __shared__ float xs[58][58];
    const int c = blockIdx.x;   // 0..63
    const int n = blockIdx.y;   // 0..15
    const int tid = threadIdx.x;

    for (int i = tid; i < 58 * 58; i += 224) ((float*)xs)[i] = 0.f;
    __syncthreads();
    const float* src = g_y + (long)n * Cc * HWc + (long)((WVAR ? 64 : 0) + c) * HWc;
    for (int i = tid; i < HWc; i += 224) {
        const int h = i / 56;
        xs[1 + h][1 + (i - h * 56)] = src[i];
    }
    __syncthreads();

    const int oo = tid >> 2;      // output row index (o or wo)
    const int grp = tid & 3;
    const int base0 = grp * 14;
    const float* wrow = Wg + ((long)c * 56 + oo) * 168;

    float acc[14];
    const float bval = __ldg(&bias[c * 56 + oo]);
#pragma unroll
    for (int i = 0; i < 14; i++) acc[i] = bval;

    if (!WVAR) {
        for (int hp = 0; hp < 56; hp++) {
            const float w0 = __ldg(&wrow[hp * 3 + 0]);
            const float w1 = __ldg(&wrow[hp * 3 + 1]);
            const float w2 = __ldg(&wrow[hp * 3 + 2]);
            float xv[16];
#pragma unroll
            for (int t = 0; t < 16; t++) xv[t] = xs[1 + hp][base0 + t];
#pragma unroll
            for (int i = 0; i < 14; i++) acc[i] += w0 * xv[i] + w1 * xv[i + 1] + w2 * xv[i + 2];
        }
        float* dst = g_cat + (long)n * C1c * HWc + (long)c * HWc + oo * 56 + base0;
#pragma unroll
        for (int i = 0; i < 14; i++) dst[i] = acc[i];
    } else {
        for (int wp = 0; wp < 56; wp++) {
            const float w0 = __ldg(&wrow[wp * 3 + 0]);
            const float w1 = __ldg(&wrow[wp * 3 + 1]);
            const float w2 = __ldg(&wrow[wp * 3 + 2]);
            float xv[16];
#pragma unroll
            for (int t = 0; t < 16; t++) xv[t] = xs[base0 + t][1 + wp];
#pragma unroll
            for (int i = 0; i < 14; i++) acc[i] += w0 * xv[i] + w1 * xv[i + 1] + w2 * xv[i + 2];
        }
        float* dst = g_cat + (long)n * C1c * HWc + (long)(64 + c) * HWc + oo;
#pragma unroll
        for (int i = 0; i < 14; i++) dst[(base0 + i) * 56] = acc[i];
    }
}

// ---------------------------------------------------------------------------
// Depthwise 3x7 (pad 1,3) + 7x3 (pad 3,1) on x2 = y[:,128:], plus channel mean
// of (x2h + x2w + x2). Block = (c, n), 256 threads.
// ---------------------------------------------------------------------------
__global__ __launch_bounds__(256)
void dw_k(const float* __restrict__ wh, const float* __restrict__ ww)
{
    __shared__ float xs[62][62];
    __shared__ float red[8];
    const int c = blockIdx.x, n = blockIdx.y;
    const int tid = threadIdx.x;

    for (int i = tid; i < 62 * 62; i += 256) ((float*)xs)[i] = 0.f;
    __syncthreads();
    const float* src = g_y + (long)n * Cc * HWc + (long)(128 + c) * HWc;
    for (int i = tid; i < HWc; i += 256) {
        const int h = i / 56;
        xs[3 + h][3 + (i - h * 56)] = src[i];
    }
    __syncthreads();

    float kh_[21], kw_[21];
#pragma unroll
    for (int i = 0; i < 21; i++) { kh_[i] = __ldg(&wh[c * 21 + i]); kw_[i] = __ldg(&ww[c * 21 + i]); }

    float lsum = 0.f;
    float* dh = g_x2h + (long)n * C1c * HWc + (long)c * HWc;
    float* dv = g_x2w + (long)n * C1c * HWc + (long)c * HWc;
    for (int i = tid; i < HWc; i += 256) {
        const int h = i / 56, w = i - h * 56;
        float vh = 0.f, vw = 0.f;
#pragma unroll
        for (int a = 0; a < 3; a++)
#pragma unroll
            for (int b = 0; b < 7; b++)
                vh += kh_[a * 7 + b] * xs[h + a + 2][w + b];
#pragma unroll
        for (int a = 0; a < 7; a++)
#pragma unroll
            for (int b = 0; b < 3; b++)
                vw += kw_[a * 3 + b] * xs[h + a][w + b + 2];
        const float x0 = xs[3 + h][3 + w];
        dh[i] = vh;
        dv[i] = vw;
        lsum += vh + vw + x0;
    }
#pragma unroll
    for (int off = 16; off; off >>= 1) lsum += __shfl_down_sync(0xffffffffu, lsum, off);
    if ((tid & 31) == 0) red[tid >> 5] = lsum;
    __syncthreads();
    if (tid == 0) {
        float s = 0.f;
#pragma unroll
        for (int i = 0; i < 8; i++) s += red[i];
        g_att[n * 128 + c] = s * (1.0f / HWc);
    }
}

// ---------------------------------------------------------------------------
// Tiny attention MLP: att[16,128] -> hidden 64 (gelu) -> 384 -> softmax over 3
// ---------------------------------------------------------------------------
__global__ __launch_bounds__(128)
void att_k(const float* __restrict__ w1, const float* __restrict__ b1,
           const float* __restrict__ w2, const float* __restrict__ b2)
{
    __shared__ float satt[128];
    __shared__ float shid[64];
    const int n = blockIdx.x, tid = threadIdx.x;
    satt[tid] = g_att[n * 128 + tid];
    __syncthreads();
    if (tid < 64) {
        float acc = b1[tid];
        for (int c = 0; c < 128; c++) acc += satt[c] * w1[tid * 128 + c];
        shid[tid] = gelu_f(acc);
    }
    __syncthreads();
    float v[3];
#pragma unroll
    for (int k = 0; k < 3; k++) {
        float acc = b2[tid * 3 + k];
        for (int h = 0; h < 64; h++) acc += shid[h] * w2[(tid * 3 + k) * 64 + h];
        v[k] = acc;
    }
    const float m = fmaxf(v[0], fmaxf(v[1], v[2]));
    const float e0 = expf(v[0] - m), e1 = expf(v[1] - m), e2 = expf(v[2] - m);
    const float s = e0 + e1 + e2;
    g_a[n * 384 + tid * 3 + 0] = e0 / s;
    g_a[n * 384 + tid * 3 + 1] = e1 / s;
    g_a[n * 384 + tid * 3 + 2] = e2 / s;
}

// ---------------------------------------------------------------------------
// x2n = x2h*a0 + x2w*a1 + x2*a2
// ---------------------------------------------------------------------------
__global__ __launch_bounds__(256)
void comb_k()
{
    const long total4 = (long)Nn * C1c * HWc / 4;
    for (long e4 = (long)blockIdx.x * 256 + threadIdx.x; e4 < total4; e4 += (long)gridDim.x * 256) {
        const long e = e4 * 4;
        const int n = (int)(e / ((long)C1c * HWc));
        const long r = e - (long)n * C1c * HWc;
        const int c = (int)(r / HWc);
        const int hw = (int)(r - (long)c * HWc);
        const float a0 = g_a[n * 384 + c * 3 + 0];
        const float a1 = g_a[n * 384 + c * 3 + 1];
        const float a2 = g_a[n * 384 + c * 3 + 2];
        const float4 h4 = *reinterpret_cast<const float4*>(&g_x2h[e]);
        const float4 w4 = *reinterpret_cast<const float4*>(&g_x2w[e]);
        const float4 x4 = *reinterpret_cast<const float4*>(&g_y[(long)n * Cc * HWc + (long)(128 + c) * HWc + hw]);
        float4 o4;
        o4.x = h4.x * a0 + w4.x * a1 + x4.x * a2;
        o4.y = h4.y * a0 + w4.y * a1 + x4.y * a2;
        o4.z = h4.z * a0 + w4.z * a1 + x4.z * a2;
        o4.w = h4.w * a0 + w4.w * a1 + x4.w * a2;
        *reinterpret_cast<float4*>(&g_x2n[e]) = o4;
    }
}

// ---------------------------------------------------------------------------
extern "C" void kernel_launch(void* const* d_in, const int* in_sizes, int n_in,
                              void* d_out, int out_size)
{
    const float* x      = (const float*)d_in[0];
    const float* mlp_w  = (const float*)d_in[1];
    const float* mlp_b  = (const float*)d_in[2];
    const float* bn1_g  = (const float*)d_in[3];
    const float* bn1_b  = (const float*)d_in[4];
    const float* bn1_m  = (const float*)d_in[5];
    const float* bn1_v  = (const float*)d_in[6];
    const float* pos_h  = (const float*)d_in[7];
    const float* pos_w  = (const float*)d_in[8];
    const float* pjh_w  = (const float*)d_in[9];
    const float* pjh_b  = (const float*)d_in[10];
    const float* pjw_w  = (const float*)d_in[11];
    const float* pjw_b  = (const float*)d_in[12];
    const float* fuse_h = (const float*)d_in[13];
    const float* bn2_g  = (const float*)d_in[14];
    const float* bn2_b  = (const float*)d_in[15];
    const float* bn2_m  = (const float*)d_in[16];
    const float* bn2_v  = (const float*)d_in[17];
    const float* fuse_w = (const float*)d_in[18];
    const float* fch_w  = (const float*)d_in[19];
    const float* fcw_w  = (const float*)d_in[20];
    const float* rw_w1  = (const float*)d_in[21];
    const float* rw_b1  = (const float*)d_in[22];
    const float* rw_w2  = (const float*)d_in[23];
    const float* rw_b2  = (const float*)d_in[24];
    const float* fout_w = (const float*)d_in[25];

    float *yp, *catp, *t1p, *u1p, *x2np;
    cudaGetSymbolAddress((void**)&yp,   g_y);
    cudaGetSymbolAddress((void**)&catp, g_cat);
    cudaGetSymbolAddress((void**)&t1p,  g_t1);
    cudaGetSymbolAddress((void**)&u1p,  g_u1);
    cudaGetSymbolAddress((void**)&x2np, g_x2n);

    const int sFull = Cc * HWc;   // 256-ch image stride
    const int sHalf = C1c * HWc;  // 128-ch image stride

    // GEMM1: y = gelu(bn(x@mlp_w + mlp_b)) ; ch<128 += pos_h
    gemm_k<1><<<dim3(Pc / 128, 2), 256>>>(mlp_w, 256, x, 256, sFull, x, sFull,
                                          yp, sFull, mlp_b, bn1_g, bn1_b, bn1_m, bn1_v, pos_h);

    // strip convs (read y ch 0..63 / 64..127, write g_cat ch 0..63 / 64..127)
    strip_k<false><<<dim3(64, 16), 224>>>(pjh_w, pjh_b);
    strip_k<true ><<<dim3(64, 16), 224>>>(pjw_w, pjw_b);

    // depthwise + channel means (reads y ch 128..255)
    dw_k<<<dim3(128, 16), 256>>>(fch_w, fcw_w);
    att_k<<<16, 128>>>(rw_w1, rw_b1, rw_w2, rw_b2);
    comb_k<<<1024, 256>>>();

    // GEMM2: t1 = gelu(bn(concat[cat, x1]@fuse_h)) + pos_w
    gemm_k<2><<<dim3(Pc / 128, 1), 256>>>(fuse_h, 256, catp, 128, sHalf, yp, sFull,
                                          t1p, sHalf, nullptr, bn2_g, bn2_b, bn2_m, bn2_v, pos_w);

    // GEMM3: u1 = concat[t1, x2]@fuse_w   (x2 = y ch 128..255 via pointer offset)
    gemm_k<0><<<dim3(Pc / 128, 1), 256>>>(fuse_w, 256, t1p, 128, sHalf, yp + 128 * HWc, sFull,
                                          u1p, sHalf, nullptr, nullptr, nullptr, nullptr, nullptr, nullptr);

    // GEMM4: out = concat[u1, x2n]@fuse_out
    gemm_k<0><<<dim3(Pc / 128, 2), 256>>>(fout_w, 256, u1p, 128, sHalf, x2np, sHalf,
                                          (float*)d_out, sFull, nullptr, nullptr, nullptr, nullptr, nullptr, nullptr);
}

// round 4
// speedup vs baseline: 1.1903x; 1.1903x over previous
#include <cuda_runtime.h>
#include <cuda_bf16.h>
#include <math.h>
#include <stdint.h>

#define Nn   16
#define Cc   256
#define C1c  128
#define HWc  3136
#define Pc   (Nn*HWc)
#define EPSf 1e-5f

// ---------------- scratch (device globals; no allocations) ----------------
__device__ float g_y  [Nn*Cc *HWc];
__device__ float g_cat[Nn*C1c*HWc];
__device__ float g_t1 [Nn*C1c*HWc];
__device__ float g_u1 [Nn*C1c*HWc];
__device__ float g_x2h[Nn*C1c*HWc];
__device__ float g_x2w[Nn*C1c*HWc];
__device__ float g_x2n[Nn*C1c*HWc];
__device__ float g_att[Nn*C1c];
__device__ float g_a  [Nn*C1c*3];

__device__ __forceinline__ float gelu_f(float x) {
    return 0.5f * x * (1.0f + erff(x * 0.7071067811865476f));
}
__device__ __forceinline__ uint32_t smem_to_u32(const void* p) {
    uint32_t a;
    asm("{ .reg .u64 t; cvta.to.shared.u64 t, %1; cvt.u32.u64 %0, t; }" : "=r"(a) : "l"(p));
    return a;
}
__device__ __forceinline__ uint32_t pack_bf2(float x0, float x1) {
    __nv_bfloat162 h = __floats2bfloat162_rn(x0, x1);
    return *reinterpret_cast<uint32_t*>(&h);
}
__device__ __forceinline__ void split_bf2(float x0, float x1, uint32_t& hi, uint32_t& lo) {
    const __nv_bfloat16 h0 = __float2bfloat16(x0);
    const __nv_bfloat16 h1 = __float2bfloat16(x1);
    const float r0 = x0 - __bfloat162float(h0);
    const float r1 = x1 - __bfloat162float(h1);
    hi = (uint32_t)__bfloat16_as_ushort(h0) | ((uint32_t)__bfloat16_as_ushort(h1) << 16);
    lo = pack_bf2(r0, r1);
}
__device__ __forceinline__ void ldsm4(uint32_t (&r)[4], uint32_t addr) {
    asm volatile("ldmatrix.sync.aligned.m8n8.x4.shared.b16 {%0,%1,%2,%3}, [%4];"
        : "=r"(r[0]), "=r"(r[1]), "=r"(r[2]), "=r"(r[3]) : "r"(addr));
}
__device__ __forceinline__ void ldsm4t(uint32_t (&r)[4], uint32_t addr) {
    asm volatile("ldmatrix.sync.aligned.m8n8.x4.trans.shared.b16 {%0,%1,%2,%3}, [%4];"
        : "=r"(r[0]), "=r"(r[1]), "=r"(r[2]), "=r"(r[3]) : "r"(addr));
}
__device__ __forceinline__ void mma16816(float (&c)[4], const uint32_t (&a)[4], uint32_t b0, uint32_t b1) {
    asm volatile("mma.sync.aligned.m16n8k16.row.col.f32.bf16.bf16.f32 "
        "{%0,%1,%2,%3}, {%4,%5,%6,%7}, {%8,%9}, {%0,%1,%2,%3};"
        : "+f"(c[0]), "+f"(c[1]), "+f"(c[2]), "+f"(c[3])
        : "r"(a[0]), "r"(a[1]), "r"(a[2]), "r"(a[3]), "r"(b0), "r"(b1));
}

// ---------------------------------------------------------------------------
// Tensor-core GEMM: out[o, q] = sum_{c<256} W[o*256+c] * in[c, q]
// Block: 128 pixels (M) x 128 out-ch (N), K=256. 256 threads = 8 warps (4m x 2n).
// 3-term bf16 split via mma.sync m16n8k16 (target-neutral PTX -> HMMA).
// SMEM: Bhi/Blo [128 n][264 k-elems]; A double-buffered [64 k][136 m-elems] hi/lo.
// Epilogue: SMEM transpose (reusing B area) -> coalesced float4 stores.
// EPI: 0 none; 1 (+bias,BN,gelu,+pos if o<128); 2 (BN,gelu,+pos)
// ---------------------------------------------------------------------------
#define RB 264
#define RA 136
#define OFF_BLO 67584
#define OFF_A   135168
#define ABUF    34816
#define SMEM_TOTAL_GEMM 204800

template<int EPI>
__global__ __launch_bounds__(256, 1)
void tc_gemm(const float* __restrict__ Wm,
             const float* __restrict__ inA, int cinA, int strA,
             const float* __restrict__ inB, int strB,
             float* __restrict__ out, int strO,
             const float* __restrict__ e_bias,
             const float* __restrict__ e_g, const float* __restrict__ e_b,
             const float* __restrict__ e_m, const float* __restrict__ e_v,
             const float* __restrict__ e_pos)
{
    extern __shared__ __align__(16) char sm[];
    __nv_bfloat16* Bhi = reinterpret_cast<__nv_bfloat16*>(sm);
    __nv_bfloat16* Blo = reinterpret_cast<__nv_bfloat16*>(sm + OFF_BLO);

    const int tid = threadIdx.x;
    const int wid = tid >> 5;
    const int lane = tid & 31;
    const int q0 = blockIdx.x * 128;
    const int o0 = blockIdx.y * 128;
    const int warp_m = (wid & 3) * 32;
    const int warp_n = (wid >> 2) * 64;

    // ---- stage B (all K=256): W rows -> [n][k] hi/lo, padded stride RB ----
    {
        const int kp = tid & 127;           // float2 index within row
        const int nb = tid >> 7;            // 0..1
        for (int i = 0; i < 64; i++) {
            const int n = nb + 2 * i;
            const float2 w2 = *reinterpret_cast<const float2*>(&Wm[(long)(o0 + n) * 256 + 2 * kp]);
            uint32_t hi, lo;
            split_bf2(w2.x, w2.y, hi, lo);
            *reinterpret_cast<uint32_t*>(&Bhi[n * RB + 2 * kp]) = hi;
            *reinterpret_cast<uint32_t*>(&Blo[n * RB + 2 * kp]) = lo;
        }
    }

    // ---- A staging geometry (fixed per thread) ----
    const int pix2 = tid & 63;              // float2 pixel pair
    const int rowb = tid >> 6;              // 0..3
    const int qA = q0 + 2 * pix2;
    const int nimgA = qA / HWc;
    const int hwA = qA - nimgA * HWc;
    const float* pSrcA = inA + (long)nimgA * strA + hwA;
    const float* pSrcB = inB + (long)nimgA * strB + hwA;

    float2 pf[16];
#define A_LOAD(KC)                                                              \
    do {                                                                        \
        _Pragma("unroll")                                                       \
        for (int i = 0; i < 16; i++) {                                          \
            const int c = (KC) * 64 + rowb + 4 * i;                             \
            const float* p = (c < cinA) ? pSrcA + (long)c * HWc                 \
                                        : pSrcB + (long)(c - cinA) * HWc;       \
            pf[i] = *reinterpret_cast<const float2*>(p);                        \
        }                                                                       \
    } while (0)
#define A_STORE(BUF)                                                            \
    do {                                                                        \
        __nv_bfloat16* Ah = reinterpret_cast<__nv_bfloat16*>(sm + OFF_A + (BUF) * ABUF); \
        __nv_bfloat16* Al = reinterpret_cast<__nv_bfloat16*>(sm + OFF_A + (BUF) * ABUF + 17408); \
        _Pragma("unroll")                                                       \
        for (int i = 0; i < 16; i++) {                                          \
            const int r = rowb + 4 * i;                                         \
            uint32_t hi, lo;                                                    \
            split_bf2(pf[i].x, pf[i].y, hi, lo);                                \
            *reinterpret_cast<uint32_t*>(&Ah[r * RA + 2 * pix2]) = hi;          \
            *reinterpret_cast<uint32_t*>(&Al[r * RA + 2 * pix2]) = lo;          \
        }                                                                       \
    } while (0)

    A_LOAD(0);
    A_STORE(0);
    __syncthreads();

    // ---- ldmatrix lane geometry ----
    const int a_kr = (lane & 7) + ((lane & 16) >> 1);   // +8 for lanes 16..31
    const int a_mc = (lane & 8);                        // +8 for bit3
    const int b_nr = (lane & 7) + ((lane & 16) >> 1);
    const int b_kc = (lane & 8);
    const uint32_t Bhi_sa = smem_to_u32(Bhi);
    const uint32_t Blo_sa = smem_to_u32(Blo);

    float acc[2][8][4];
#pragma unroll
    for (int mt = 0; mt < 2; mt++)
#pragma unroll
        for (int nf = 0; nf < 8; nf++)
#pragma unroll
            for (int j = 0; j < 4; j++) acc[mt][nf][j] = 0.f;

    for (int kc = 0; kc < 4; kc++) {
        const int cur = kc & 1;
        if (kc < 3) A_LOAD(kc + 1);

        const uint32_t Ah_sa = smem_to_u32(sm + OFF_A + cur * ABUF);
        const uint32_t Al_sa = Ah_sa + 17408;

#pragma unroll
        for (int ks = 0; ks < 4; ks++) {
            const int k0 = ks * 16;
            const int kg = kc * 64 + k0;
            uint32_t ah[2][4], al[2][4];
#pragma unroll
            for (int half = 0; half < 2; half++) {
                const uint32_t ea = (uint32_t)((k0 + a_kr) * RA + warp_m + half * 16 + a_mc) * 2;
                ldsm4t(ah[half], Ah_sa + ea);
                ldsm4t(al[half], Al_sa + ea);
            }
            uint32_t bh[8][2], bl[8][2];
#pragma unroll
            for (int ng = 0; ng < 4; ng++) {
                const uint32_t eb = (uint32_t)((warp_n + ng * 16 + b_nr) * RB + kg + b_kc) * 2;
                uint32_t t[4];
                ldsm4(t, Bhi_sa + eb);
                bh[2 * ng][0] = t[0]; bh[2 * ng][1] = t[1];
                bh[2 * ng + 1][0] = t[2]; bh[2 * ng + 1][1] = t[3];
                ldsm4(t, Blo_sa + eb);
                bl[2 * ng][0] = t[0]; bl[2 * ng][1] = t[1];
                bl[2 * ng + 1][0] = t[2]; bl[2 * ng + 1][1] = t[3];
            }
#pragma unroll
            for (int mt = 0; mt < 2; mt++)
#pragma unroll
                for (int nf = 0; nf < 8; nf++) {
                    mma16816(acc[mt][nf], ah[mt], bh[nf][0], bh[nf][1]);
                    mma16816(acc[mt][nf], ah[mt], bl[nf][0], bl[nf][1]);
                    mma16816(acc[mt][nf], al[mt], bh[nf][0], bh[nf][1]);
                }
        }
        if (kc < 3) A_STORE(cur ^ 1);
        __syncthreads();
    }

    // ---- epilogue: transpose through SMEM (reuse B area), coalesced stores ----
    float* O = reinterpret_cast<float*>(sm);   // [128 n][132 m]
#pragma unroll
    for (int mt = 0; mt < 2; mt++)
#pragma unroll
        for (int nf = 0; nf < 8; nf++) {
            const int n = warp_n + nf * 8 + (lane & 3) * 2;
            const int m = warp_m + mt * 16 + (lane >> 2);
            O[n * 132 + m]           = acc[mt][nf][0];
            O[(n + 1) * 132 + m]     = acc[mt][nf][1];
            O[n * 132 + m + 8]       = acc[mt][nf][2];
            O[(n + 1) * 132 + m + 8] = acc[mt][nf][3];
        }
    __syncthreads();

    {
        const int m0 = lane * 4;
        const int q = q0 + m0;
        const int nimg = q / HWc;
        const int hw = q - nimg * HWc;
        int rel[4];
#pragma unroll
        for (int j = 0; j < 4; j++) {
            const int hwj = hw + j;
            const int h = hwj / 56;
            rel[j] = (hwj - h * 56) - h + 56;
        }
#pragma unroll
        for (int r = 0; r < 16; r++) {
            const int n = wid * 16 + r;
            const int o = o0 + n;
            float4 v = *reinterpret_cast<const float4*>(&O[n * 132 + m0]);
            float vv[4] = {v.x, v.y, v.z, v.w};
            if (EPI == 1) {
                const float s = __ldg(&e_g[o]) * rsqrtf(__ldg(&e_v[o]) + EPSf);
                const float t = __ldg(&e_b[o]) - __ldg(&e_m[o]) * s;
                const float bb = __ldg(&e_bias[o]);
#pragma unroll
                for (int j = 0; j < 4; j++) {
                    float u = gelu_f((vv[j] + bb) * s + t);
                    if (o < 128) u += __ldg(&e_pos[rel[j] * 128 + o]);
                    vv[j] = u;
                }
            } else if (EPI == 2) {
                const float s = __ldg(&e_g[o]) * rsqrtf(__ldg(&e_v[o]) + EPSf);
                const float t = __ldg(&e_b[o]) - __ldg(&e_m[o]) * s;
#pragma unroll
                for (int j = 0; j < 4; j++)
                    vv[j] = gelu_f(vv[j] * s + t) + __ldg(&e_pos[rel[j] * 128 + o]);
            }
            float4 ov; ov.x = vv[0]; ov.y = vv[1]; ov.z = vv[2]; ov.w = vv[3];
            *reinterpret_cast<float4*>(&out[(long)nimg * strO + (long)o * HWc + hw]) = ov;
        }
    }
#undef A_LOAD
#undef A_STORE
}

// ---------------------------------------------------------------------------
// Strip conv (unchanged).
// ---------------------------------------------------------------------------
template<bool WVAR>
__global__ __launch_bounds__(224)
void strip_k(const float* __restrict__ Wg, const float* __restrict__ bias)
{
    __shared__ float xs[58][58];
    const int c = blockIdx.x, n = blockIdx.y;
    const int tid = threadIdx.x;

    for (int i = tid; i < 58 * 58; i += 224) ((float*)xs)[i] = 0.f;
    __syncthreads();
    const float* src = g_y + (long)n * Cc * HWc + (long)((WVAR ? 64 : 0) + c) * HWc;
    for (int i = tid; i < HWc; i += 224) {
        const int h = i / 56;
        xs[1 + h][1 + (i - h * 56)] = src[i];
    }
    __syncthreads();

    const int oo = tid >> 2;
    const int base0 = (tid & 3) * 14;
    const float* wrow = Wg + ((long)c * 56 + oo) * 168;

    float acc[14];
    const float bval = __ldg(&bias[c * 56 + oo]);
#pragma unroll
    for (int i = 0; i < 14; i++) acc[i] = bval;

    if (!WVAR) {
        for (int hp = 0; hp < 56; hp++) {
            const float w0 = __ldg(&wrow[hp * 3 + 0]);
            const float w1 = __ldg(&wrow[hp * 3 + 1]);
            const float w2 = __ldg(&wrow[hp * 3 + 2]);
            float xv[16];
#pragma unroll
            for (int t = 0; t < 16; t++) xv[t] = xs[1 + hp][base0 + t];
#pragma unroll
            for (int i = 0; i < 14; i++) acc[i] += w0 * xv[i] + w1 * xv[i + 1] + w2 * xv[i + 2];
        }
        float* dst = g_cat + (long)n * C1c * HWc + (long)c * HWc + oo * 56 + base0;
#pragma unroll
        for (int i = 0; i < 14; i++) dst[i] = acc[i];
    } else {
        for (int wp = 0; wp < 56; wp++) {
            const float w0 = __ldg(&wrow[wp * 3 + 0]);
            const float w1 = __ldg(&wrow[wp * 3 + 1]);
            const float w2 = __ldg(&wrow[wp * 3 + 2]);
            float xv[16];
#pragma unroll
            for (int t = 0; t < 16; t++) xv[t] = xs[base0 + t][1 + wp];
#pragma unroll
            for (int i = 0; i < 14; i++) acc[i] += w0 * xv[i] + w1 * xv[i + 1] + w2 * xv[i + 2];
        }
        float* dst = g_cat + (long)n * C1c * HWc + (long)(64 + c) * HWc + oo;
#pragma unroll
        for (int i = 0; i < 14; i++) dst[(base0 + i) * 56] = acc[i];
    }
}

// ---------------------------------------------------------------------------
// Depthwise 3x7 + 7x3 on x2, plus channel mean (unchanged).
// ---------------------------------------------------------------------------
__global__ __launch_bounds__(256)
void dw_k(const float* __restrict__ wh, const float* __restrict__ ww)
{
    __shared__ float xs[62][62];
    __shared__ float red[8];
    const int c = blockIdx.x, n = blockIdx.y;
    const int tid = threadIdx.x;

    for (int i = tid; i < 62 * 62; i += 256) ((float*)xs)[i] = 0.f;
    __syncthreads();
    const float* src = g_y + (long)n * Cc * HWc + (long)(128 + c) * HWc;
    for (int i = tid; i < HWc; i += 256) {
        const int h = i / 56;
        xs[3 + h][3 + (i - h * 56)] = src[i];
    }
    __syncthreads();

    float kh_[21], kw_[21];
#pragma unroll
    for (int i = 0; i < 21; i++) { kh_[i] = __ldg(&wh[c * 21 + i]); kw_[i] = __ldg(&ww[c * 21 + i]); }

    float lsum = 0.f;
    float* dh = g_x2h + (long)n * C1c * HWc + (long)c * HWc;
    float* dv = g_x2w + (long)n * C1c * HWc + (long)c * HWc;
    for (int i = tid; i < HWc; i += 256) {
        const int h = i / 56, w = i - h * 56;
        float vh = 0.f, vw = 0.f;
#pragma unroll
        for (int a = 0; a < 3; a++)
#pragma unroll
            for (int b = 0; b < 7; b++)
                vh += kh_[a * 7 + b] * xs[h + a + 2][w + b];
#pragma unroll
        for (int a = 0; a < 7; a++)
#pragma unroll
            for (int b = 0; b < 3; b++)
                vw += kw_[a * 3 + b] * xs[h + a][w + b + 2];
        const float x0 = xs[3 + h][3 + w];
        dh[i] = vh;
        dv[i] = vw;
        lsum += vh + vw + x0;
    }
#pragma unroll
    for (int off = 16; off; off >>= 1) lsum += __shfl_down_sync(0xffffffffu, lsum, off);
    if ((tid & 31) == 0) red[tid >> 5] = lsum;
    __syncthreads();
    if (tid == 0) {
        float s = 0.f;
#pragma unroll
        for (int i = 0; i < 8; i++) s += red[i];
        g_att[n * 128 + c] = s * (1.0f / HWc);
    }
}

// ---------------------------------------------------------------------------
// Tiny attention MLP (unchanged).
// ---------------------------------------------------------------------------
__global__ __launch_bounds__(128)
void att_k(const float* __restrict__ w1, const float* __restrict__ b1,
           const float* __restrict__ w2, const float* __restrict__ b2)
{
    __shared__ float satt[128];
    __shared__ float shid[64];
    const int n = blockIdx.x, tid = threadIdx.x;
    satt[tid] = g_att[n * 128 + tid];
    __syncthreads();
    if (tid < 64) {
        float acc = b1[tid];
        for (int c = 0; c < 128; c++) acc += satt[c] * w1[tid * 128 + c];
        shid[tid] = gelu_f(acc);
    }
    __syncthreads();
    float v[3];
#pragma unroll
    for (int k = 0; k < 3; k++) {
        float acc = b2[tid * 3 + k];
        for (int h = 0; h < 64; h++) acc += shid[h] * w2[(tid * 3 + k) * 64 + h];
        v[k] = acc;
    }
    const float m = fmaxf(v[0], fmaxf(v[1], v[2]));
    const float e0 = expf(v[0] - m), e1 = expf(v[1] - m), e2 = expf(v[2] - m);
    const float s = e0 + e1 + e2;
    g_a[n * 384 + tid * 3 + 0] = e0 / s;
    g_a[n * 384 + tid * 3 + 1] = e1 / s;
    g_a[n * 384 + tid * 3 + 2] = e2 / s;
}

// ---------------------------------------------------------------------------
// x2n = x2h*a0 + x2w*a1 + x2*a2 (unchanged).
// ---------------------------------------------------------------------------
__global__ __launch_bounds__(256)
void comb_k()
{
    const long total4 = (long)Nn * C1c * HWc / 4;
    for (long e4 = (long)blockIdx.x * 256 + threadIdx.x; e4 < total4; e4 += (long)gridDim.x * 256) {
        const long e = e4 * 4;
        const int n = (int)(e / ((long)C1c * HWc));
        const long r = e - (long)n * C1c * HWc;
        const int c = (int)(r / HWc);
        const int hw = (int)(r - (long)c * HWc);
        const float a0 = g_a[n * 384 + c * 3 + 0];
        const float a1 = g_a[n * 384 + c * 3 + 1];
        const float a2 = g_a[n * 384 + c * 3 + 2];
        const float4 h4 = *reinterpret_cast<const float4*>(&g_x2h[e]);
        const float4 w4 = *reinterpret_cast<const float4*>(&g_x2w[e]);
        const float4 x4 = *reinterpret_cast<const float4*>(&g_y[(long)n * Cc * HWc + (long)(128 + c) * HWc + hw]);
        float4 o4;
        o4.x = h4.x * a0 + w4.x * a1 + x4.x * a2;
        o4.y = h4.y * a0 + w4.y * a1 + x4.y * a2;
        o4.z = h4.z * a0 + w4.z * a1 + x4.z * a2;
        o4.w = h4.w * a0 + w4.w * a1 + x4.w * a2;
        *reinterpret_cast<float4*>(&g_x2n[e]) = o4;
    }
}

// ---------------------------------------------------------------------------
extern "C" void kernel_launch(void* const* d_in, const int* in_sizes, int n_in,
                              void* d_out, int out_size)
{
    const float* x      = (const float*)d_in[0];
    const float* mlp_w  = (const float*)d_in[1];
    const float* mlp_b  = (const float*)d_in[2];
    const float* bn1_g  = (const float*)d_in[3];
    const float* bn1_b  = (const float*)d_in[4];
    const float* bn1_m  = (const float*)d_in[5];
    const float* bn1_v  = (const float*)d_in[6];
    const float* pos_h  = (const float*)d_in[7];
    const float* pos_w  = (const float*)d_in[8];
    const float* pjh_w  = (const float*)d_in[9];
    const float* pjh_b  = (const float*)d_in[10];
    const float* pjw_w  = (const float*)d_in[11];
    const float* pjw_b  = (const float*)d_in[12];
    const float* fuse_h = (const float*)d_in[13];
    const float* bn2_g  = (const float*)d_in[14];
    const float* bn2_b  = (const float*)d_in[15];
    const float* bn2_m  = (const float*)d_in[16];
    const float* bn2_v  = (const float*)d_in[17];
    const float* fuse_w = (const float*)d_in[18];
    const float* fch_w  = (const float*)d_in[19];
    const float* fcw_w  = (const float*)d_in[20];
    const float* rw_w1  = (const float*)d_in[21];
    const float* rw_b1  = (const float*)d_in[22];
    const float* rw_w2  = (const float*)d_in[23];
    const float* rw_b2  = (const float*)d_in[24];
    const float* fout_w = (const float*)d_in[25];

    float *yp, *catp, *t1p, *u1p, *x2np;
    cudaGetSymbolAddress((void**)&yp,   g_y);
    cudaGetSymbolAddress((void**)&catp, g_cat);
    cudaGetSymbolAddress((void**)&t1p,  g_t1);
    cudaGetSymbolAddress((void**)&u1p,  g_u1);
    cudaGetSymbolAddress((void**)&x2np, g_x2n);

    const int sFull = Cc * HWc;
    const int sHalf = C1c * HWc;

    cudaFuncSetAttribute(tc_gemm<0>, cudaFuncAttributeMaxDynamicSharedMemorySize, SMEM_TOTAL_GEMM);
    cudaFuncSetAttribute(tc_gemm<1>, cudaFuncAttributeMaxDynamicSharedMemorySize, SMEM_TOTAL_GEMM);
    cudaFuncSetAttribute(tc_gemm<2>, cudaFuncAttributeMaxDynamicSharedMemorySize, SMEM_TOTAL_GEMM);

    // GEMM1: y = gelu(bn(x@mlp_w + mlp_b)) ; ch<128 += pos_h
    tc_gemm<1><<<dim3(Pc / 128, 2), 256, SMEM_TOTAL_GEMM>>>(mlp_w, x, 256, sFull, x, sFull,
        yp, sFull, mlp_b, bn1_g, bn1_b, bn1_m, bn1_v, pos_h);

    // strip convs + depthwise + attention + recombine
    strip_k<false><<<dim3(64, 16), 224>>>(pjh_w, pjh_b);
    strip_k<true ><<<dim3(64, 16), 224>>>(pjw_w, pjw_b);
    dw_k<<<dim3(128, 16), 256>>>(fch_w, fcw_w);
    att_k<<<16, 128>>>(rw_w1, rw_b1, rw_w2, rw_b2);
    comb_k<<<1024, 256>>>();

    // GEMM2: t1 = gelu(bn(concat[cat, x1]@fuse_h)) + pos_w
    tc_gemm<2><<<dim3(Pc / 128, 1), 256, SMEM_TOTAL_GEMM>>>(fuse_h, catp, 128, sHalf, yp, sFull,
        t1p, sHalf, nullptr, bn2_g, bn2_b, bn2_m, bn2_v, pos_w);

    // GEMM3: u1 = concat[t1, x2]@fuse_w
    tc_gemm<0><<<dim3(Pc / 128, 1), 256, SMEM_TOTAL_GEMM>>>(fuse_w, t1p, 128, sHalf, yp + 128 * HWc, sFull,
        u1p, sHalf, nullptr, nullptr, nullptr, nullptr, nullptr, nullptr);

    // GEMM4: out = concat[u1, x2n]@fuse_out
    tc_gemm<0><<<dim3(Pc / 128, 2), 256, SMEM_TOTAL_GEMM>>>(fout_w, u1p, 128, sHalf, x2np, sHalf,
        (float*)d_out, sFull, nullptr, nullptr, nullptr, nullptr, nullptr, nullptr);
}

// round 5
// speedup vs baseline: 1.2545x; 1.0540x over previous
#include <cuda_runtime.h>
#include <cuda_bf16.h>
#include <math.h>
#include <stdint.h>

#define Nn   16
#define Cc   256
#define C1c  128
#define HWc  3136
#define Pc   (Nn*HWc)
#define EPSf 1e-5f

// ---------------- scratch (device globals; no allocations) ----------------
__device__ float g_y  [Nn*Cc *HWc];
__device__ float g_cat[Nn*C1c*HWc];
__device__ float g_t1 [Nn*C1c*HWc];
__device__ float g_u1 [Nn*C1c*HWc];
__device__ float g_x2h[Nn*C1c*HWc];
__device__ float g_x2w[Nn*C1c*HWc];
__device__ float g_att[Nn*C1c];
__device__ float g_a  [Nn*C1c*3];

__device__ __forceinline__ float gelu_f(float x) {
    return 0.5f * x * (1.0f + erff(x * 0.7071067811865476f));
}
__device__ __forceinline__ uint32_t smem_to_u32(const void* p) {
    uint32_t a;
    asm("{ .reg .u64 t; cvta.to.shared.u64 t, %1; cvt.u32.u64 %0, t; }" : "=r"(a) : "l"(p));
    return a;
}
__device__ __forceinline__ uint32_t pack_bf2(float x0, float x1) {
    __nv_bfloat162 h = __floats2bfloat162_rn(x0, x1);
    return *reinterpret_cast<uint32_t*>(&h);
}
__device__ __forceinline__ void split_bf2(float x0, float x1, uint32_t& hi, uint32_t& lo) {
    const __nv_bfloat16 h0 = __float2bfloat16(x0);
    const __nv_bfloat16 h1 = __float2bfloat16(x1);
    const float r0 = x0 - __bfloat162float(h0);
    const float r1 = x1 - __bfloat162float(h1);
    hi = (uint32_t)__bfloat16_as_ushort(h0) | ((uint32_t)__bfloat16_as_ushort(h1) << 16);
    lo = pack_bf2(r0, r1);
}
__device__ __forceinline__ void ldsm4(uint32_t (&r)[4], uint32_t addr) {
    asm volatile("ldmatrix.sync.aligned.m8n8.x4.shared.b16 {%0,%1,%2,%3}, [%4];"
        : "=r"(r[0]), "=r"(r[1]), "=r"(r[2]), "=r"(r[3]) : "r"(addr));
}
__device__ __forceinline__ void ldsm4t(uint32_t (&r)[4], uint32_t addr) {
    asm volatile("ldmatrix.sync.aligned.m8n8.x4.trans.shared.b16 {%0,%1,%2,%3}, [%4];"
        : "=r"(r[0]), "=r"(r[1]), "=r"(r[2]), "=r"(r[3]) : "r"(addr));
}
__device__ __forceinline__ void mma16816(float (&c)[4], const uint32_t (&a)[4], uint32_t b0, uint32_t b1) {
    asm volatile("mma.sync.aligned.m16n8k16.row.col.f32.bf16.bf16.f32 "
        "{%0,%1,%2,%3}, {%4,%5,%6,%7}, {%8,%9}, {%0,%1,%2,%3};"
        : "+f"(c[0]), "+f"(c[1]), "+f"(c[2]), "+f"(c[3])
        : "r"(a[0]), "r"(a[1]), "r"(a[2]), "r"(a[3]), "r"(b0), "r"(b1));
}

// ---------------------------------------------------------------------------
// Tensor-core GEMM: out[o, q] = sum_{c<256} W[o*256+c] * in[c, q]
// Block 128 pixels (M) x 128 out-ch (N), K=256 in four 64-K chunks, 8 warps.
// Single-buffered smem (70KB) -> 2 CTAs/SM for cross-CTA latency hiding.
// 3-term bf16 split: Ahi*Bhi + Alo*Bhi + Ahi*Blo, fp32 accumulate.
// COMB=true: channels >= cinA are a0*cH + a1*cW + a2*cX computed on the fly.
// EPI: 0 none; 1 (+bias,BN,gelu,+pos if o<128); 2 (BN,gelu,+pos)
// ---------------------------------------------------------------------------
#define RA  136
#define RBc 72
#define A_L_OFF 17408
#define B_H_OFF 34816
#define B_L_OFF 53248
#define SMEM_GEMM 71680

template<int EPI, bool COMB>
__global__ __launch_bounds__(256, 2)
void tc_gemm(const float* __restrict__ Wm,
             const float* __restrict__ inA, int cinA, int strA,
             const float* __restrict__ inB, int strB,
             float* __restrict__ out, int strO,
             const float* __restrict__ e_bias,
             const float* __restrict__ e_g, const float* __restrict__ e_b,
             const float* __restrict__ e_m, const float* __restrict__ e_v,
             const float* __restrict__ e_pos,
             const float* __restrict__ cH, const float* __restrict__ cW,
             const float* __restrict__ cX, int strX,
             const float* __restrict__ cA)
{
    extern __shared__ __align__(16) char sm[];
    __nv_bfloat16* Ah = reinterpret_cast<__nv_bfloat16*>(sm);
    __nv_bfloat16* Al = reinterpret_cast<__nv_bfloat16*>(sm + A_L_OFF);
    __nv_bfloat16* Bh = reinterpret_cast<__nv_bfloat16*>(sm + B_H_OFF);
    __nv_bfloat16* Bl = reinterpret_cast<__nv_bfloat16*>(sm + B_L_OFF);

    const int tid = threadIdx.x;
    const int wid = tid >> 5;
    const int lane = tid & 31;
    const int q0 = blockIdx.x * 128;
    const int o0 = blockIdx.y * 128;
    const int warp_m = (wid & 3) * 32;
    const int warp_n = (wid >> 2) * 64;

    // A staging geometry
    const int pix2 = tid & 63;
    const int rowb = tid >> 6;
    const int qA = q0 + 2 * pix2;
    const int nimgA = qA / HWc;
    const int hwA = qA - nimgA * HWc;
    const float* pSrcA = inA + (long)nimgA * strA + hwA;
    const float* pSrcB = COMB ? nullptr : inB + (long)nimgA * strB + hwA;
    const float* pH = COMB ? cH + (long)nimgA * (C1c * HWc) + hwA : nullptr;
    const float* pW = COMB ? cW + (long)nimgA * (C1c * HWc) + hwA : nullptr;
    const float* pX = COMB ? cX + (long)nimgA * strX + hwA : nullptr;
    const float* aBase = COMB ? cA + nimgA * 384 : nullptr;

    // B staging geometry
    const int n_b = tid & 127;
    const int kb = (tid >> 7) * 32;
    const float* wRow = Wm + (long)(o0 + n_b) * 256;

    // ldmatrix lane geometry
    const int a_kr = (lane & 7) + ((lane & 16) >> 1);
    const int a_mc = (lane & 8);
    const int b_nr = (lane & 7) + ((lane & 16) >> 1);
    const int b_kc = (lane & 8);
    const uint32_t Ah_sa = smem_to_u32(Ah);
    const uint32_t Al_sa = Ah_sa + A_L_OFF;
    const uint32_t Bh_sa = Ah_sa + B_H_OFF;
    const uint32_t Bl_sa = Ah_sa + B_L_OFF;

    float acc[2][8][4];
#pragma unroll
    for (int mt = 0; mt < 2; mt++)
#pragma unroll
        for (int nf = 0; nf < 8; nf++)
#pragma unroll
            for (int j = 0; j < 4; j++) acc[mt][nf][j] = 0.f;

    for (int kc = 0; kc < 4; kc++) {
        __syncthreads();   // previous chunk's compute done before overwrite

        // ---- stage A chunk (64 k-rows x 128 m) ----
#pragma unroll
        for (int i = 0; i < 16; i++) {
            const int k = rowb + 4 * i;
            const int c = kc * 64 + k;
            float2 v;
            if (!COMB) {
                const float* p = (c < cinA) ? pSrcA + (long)c * HWc
                                            : pSrcB + (long)(c - cinA) * HWc;
                v = *reinterpret_cast<const float2*>(p);
            } else {
                if (c < cinA) {
                    v = *reinterpret_cast<const float2*>(pSrcA + (long)c * HWc);
                } else {
                    const int cc = c - cinA;
                    const float a0 = aBase[cc * 3 + 0];
                    const float a1 = aBase[cc * 3 + 1];
                    const float a2 = aBase[cc * 3 + 2];
                    const float2 vh = *reinterpret_cast<const float2*>(pH + (long)cc * HWc);
                    const float2 vw = *reinterpret_cast<const float2*>(pW + (long)cc * HWc);
                    const float2 vx = *reinterpret_cast<const float2*>(pX + (long)cc * HWc);
                    v.x = a0 * vh.x + a1 * vw.x + a2 * vx.x;
                    v.y = a0 * vh.y + a1 * vw.y + a2 * vx.y;
                }
            }
            uint32_t hi, lo;
            split_bf2(v.x, v.y, hi, lo);
            *reinterpret_cast<uint32_t*>(&Ah[k * RA + 2 * pix2]) = hi;
            *reinterpret_cast<uint32_t*>(&Al[k * RA + 2 * pix2]) = lo;
        }
        // ---- stage B chunk (128 n x 64 k) ----
#pragma unroll
        for (int j = 0; j < 8; j++) {
            const int kq = kb + 4 * j;
            const float4 w4 = *reinterpret_cast<const float4*>(&wRow[kc * 64 + kq]);
            uint32_t h01, l01, h23, l23;
            split_bf2(w4.x, w4.y, h01, l01);
            split_bf2(w4.z, w4.w, h23, l23);
            *reinterpret_cast<uint32_t*>(&Bh[n_b * RBc + kq])     = h01;
            *reinterpret_cast<uint32_t*>(&Bh[n_b * RBc + kq + 2]) = h23;
            *reinterpret_cast<uint32_t*>(&Bl[n_b * RBc + kq])     = l01;
            *reinterpret_cast<uint32_t*>(&Bl[n_b * RBc + kq + 2]) = l23;
        }
        __syncthreads();

        // ---- compute chunk: 4 k-steps of 16 ----
#pragma unroll
        for (int ks = 0; ks < 4; ks++) {
            const int k0 = ks * 16;
            uint32_t ah[2][4], al[2][4];
#pragma unroll
            for (int half = 0; half < 2; half++) {
                const uint32_t ea = (uint32_t)((k0 + a_kr) * RA + warp_m + half * 16 + a_mc) * 2;
                ldsm4t(ah[half], Ah_sa + ea);
                ldsm4t(al[half], Al_sa + ea);
            }
#pragma unroll
            for (int ng = 0; ng < 4; ng++) {
                const uint32_t eb = (uint32_t)((warp_n + ng * 16 + b_nr) * RBc + k0 + b_kc) * 2;
                uint32_t th[4], tl[4];
                ldsm4(th, Bh_sa + eb);
                ldsm4(tl, Bl_sa + eb);
#pragma unroll
                for (int mt = 0; mt < 2; mt++) {
                    mma16816(acc[mt][2 * ng],     ah[mt], th[0], th[1]);
                    mma16816(acc[mt][2 * ng],     al[mt], th[0], th[1]);
                    mma16816(acc[mt][2 * ng],     ah[mt], tl[0], tl[1]);
                    mma16816(acc[mt][2 * ng + 1], ah[mt], th[2], th[3]);
                    mma16816(acc[mt][2 * ng + 1], al[mt], th[2], th[3]);
                    mma16816(acc[mt][2 * ng + 1], ah[mt], tl[2], tl[3]);
                }
            }
        }
    }

    // ---- epilogue: transpose through SMEM, coalesced float4 stores ----
    __syncthreads();
    float* O = reinterpret_cast<float*>(sm);   // [128 n][132 m]
#pragma unroll
    for (int mt = 0; mt < 2; mt++)
#pragma unroll
        for (int nf = 0; nf < 8; nf++) {
            const int n = warp_n + nf * 8 + (lane & 3) * 2;
            const int m = warp_m + mt * 16 + (lane >> 2);
            O[n * 132 + m]           = acc[mt][nf][0];
            O[(n + 1) * 132 + m]     = acc[mt][nf][1];
            O[n * 132 + m + 8]       = acc[mt][nf][2];
            O[(n + 1) * 132 + m + 8] = acc[mt][nf][3];
        }
    __syncthreads();

    {
        const int m0 = lane * 4;
        const int q = q0 + m0;
        const int nimg = q / HWc;
        const int hw = q - nimg * HWc;
        int rel[4];
#pragma unroll
        for (int j = 0; j < 4; j++) {
            const int hwj = hw + j;
            const int h = hwj / 56;
            rel[j] = (hwj - h * 56) - h + 56;
        }
#pragma unroll
        for (int r = 0; r < 16; r++) {
            const int n = wid * 16 + r;
            const int o = o0 + n;
            float4 v = *reinterpret_cast<const float4*>(&O[n * 132 + m0]);
            float vv[4] = {v.x, v.y, v.z, v.w};
            if (EPI == 1) {
                const float s = __ldg(&e_g[o]) * rsqrtf(__ldg(&e_v[o]) + EPSf);
                const float t = __ldg(&e_b[o]) - __ldg(&e_m[o]) * s;
                const float bb = __ldg(&e_bias[o]);
#pragma unroll
                for (int j = 0; j < 4; j++) {
                    float u = gelu_f((vv[j] + bb) * s + t);
                    if (o < 128) u += __ldg(&e_pos[rel[j] * 128 + o]);
                    vv[j] = u;
                }
            } else if (EPI == 2) {
                const float s = __ldg(&e_g[o]) * rsqrtf(__ldg(&e_v[o]) + EPSf);
                const float t = __ldg(&e_b[o]) - __ldg(&e_m[o]) * s;
#pragma unroll
                for (int j = 0; j < 4; j++)
                    vv[j] = gelu_f(vv[j] * s + t) + __ldg(&e_pos[rel[j] * 128 + o]);
            }
            float4 ov; ov.x = vv[0]; ov.y = vv[1]; ov.z = vv[2]; ov.w = vv[3];
            *reinterpret_cast<float4*>(&out[(long)nimg * strO + (long)o * HWc + hw]) = ov;
        }
    }
}

// ---------------------------------------------------------------------------
// Strip conv (unchanged).
// ---------------------------------------------------------------------------
template<bool WVAR>
__global__ __launch_bounds__(224)
void strip_k(const float* __restrict__ Wg, const float* __restrict__ bias)
{
    __shared__ float xs[58][58];
    const int c = blockIdx.x, n = blockIdx.y;
    const int tid = threadIdx.x;

    for (int i = tid; i < 58 * 58; i += 224) ((float*)xs)[i] = 0.f;
    __syncthreads();
    const float* src = g_y + (long)n * Cc * HWc + (long)((WVAR ? 64 : 0) + c) * HWc;
    for (int i = tid; i < HWc; i += 224) {
        const int h = i / 56;
        xs[1 + h][1 + (i - h * 56)] = src[i];
    }
    __syncthreads();

    const int oo = tid >> 2;
    const int base0 = (tid & 3) * 14;
    const float* wrow = Wg + ((long)c * 56 + oo) * 168;

    float acc[14];
    const float bval = __ldg(&bias[c * 56 + oo]);
#pragma unroll
    for (int i = 0; i < 14; i++) acc[i] = bval;

    if (!WVAR) {
        for (int hp = 0; hp < 56; hp++) {
            const float w0 = __ldg(&wrow[hp * 3 + 0]);
            const float w1 = __ldg(&wrow[hp * 3 + 1]);
            const float w2 = __ldg(&wrow[hp * 3 + 2]);
            float xv[16];
#pragma unroll
            for (int t = 0; t < 16; t++) xv[t] = xs[1 + hp][base0 + t];
#pragma unroll
            for (int i = 0; i < 14; i++) acc[i] += w0 * xv[i] + w1 * xv[i + 1] + w2 * xv[i + 2];
        }
        float* dst = g_cat + (long)n * C1c * HWc + (long)c * HWc + oo * 56 + base0;
#pragma unroll
        for (int i = 0; i < 14; i++) dst[i] = acc[i];
    } else {
        for (int wp = 0; wp < 56; wp++) {
            const float w0 = __ldg(&wrow[wp * 3 + 0]);
            const float w1 = __ldg(&wrow[wp * 3 + 1]);
            const float w2 = __ldg(&wrow[wp * 3 + 2]);
            float xv[16];
#pragma unroll
            for (int t = 0; t < 16; t++) xv[t] = xs[base0 + t][1 + wp];
#pragma unroll
            for (int i = 0; i < 14; i++) acc[i] += w0 * xv[i] + w1 * xv[i + 1] + w2 * xv[i + 2];
        }
        float* dst = g_cat + (long)n * C1c * HWc + (long)(64 + c) * HWc + oo;
#pragma unroll
        for (int i = 0; i < 14; i++) dst[(base0 + i) * 56] = acc[i];
    }
}

// ---------------------------------------------------------------------------
// Depthwise 3x7 + 7x3 + channel mean, register-sliding windows.
// 224 threads: w = tid%56 column, strip = tid/56 -> 14 output rows each.
// ---------------------------------------------------------------------------
__global__ __launch_bounds__(224)
void dw_k(const float* __restrict__ wh, const float* __restrict__ ww)
{
    __shared__ float xs[62][62];
    __shared__ float red[7];
    const int c = blockIdx.x, n = blockIdx.y;
    const int tid = threadIdx.x;

    for (int i = tid; i < 62 * 62; i += 224) ((float*)xs)[i] = 0.f;
    __syncthreads();
    const float* src = g_y + (long)n * Cc * HWc + (long)(128 + c) * HWc;
    for (int i = tid; i < HWc; i += 224) {
        const int h = i / 56;
        xs[3 + h][3 + (i - h * 56)] = src[i];
    }
    __syncthreads();

    float kh_[21], kw_[21];
#pragma unroll
    for (int i = 0; i < 21; i++) { kh_[i] = __ldg(&wh[c * 21 + i]); kw_[i] = __ldg(&ww[c * 21 + i]); }

    const int w = tid % 56;
    const int r0 = (tid / 56) * 14;

    // sliding windows: R = 3 rows x 7 cols (3x7 conv), V = 7 rows x 3 cols (7x3 conv)
    float R[3][7], V[7][3];
#pragma unroll
    for (int a = 0; a < 3; a++)
#pragma unroll
        for (int b = 0; b < 7; b++) R[a][b] = xs[2 + r0 + a][w + b];
#pragma unroll
    for (int a = 0; a < 7; a++)
#pragma unroll
        for (int b = 0; b < 3; b++) V[a][b] = xs[r0 + a][2 + w + b];

    float lsum = 0.f;
    float* dh = g_x2h + (long)n * C1c * HWc + (long)c * HWc + w;
    float* dv = g_x2w + (long)n * C1c * HWc + (long)c * HWc + w;

#pragma unroll
    for (int j = 0; j < 14; j++) {
        float vh = 0.f, vw = 0.f;
#pragma unroll
        for (int a = 0; a < 3; a++)
#pragma unroll
            for (int b = 0; b < 7; b++)
                vh += kh_[a * 7 + b] * R[(j + a) % 3][b];
#pragma unroll
        for (int a = 0; a < 7; a++)
#pragma unroll
            for (int b = 0; b < 3; b++)
                vw += kw_[a * 3 + b] * V[(j + a) % 7][b];
        const float cen = R[(j + 1) % 3][3];
        dh[(r0 + j) * 56] = vh;
        dv[(r0 + j) * 56] = vw;
        lsum += vh + vw + cen;
        if (j < 13) {
#pragma unroll
            for (int b = 0; b < 7; b++) R[j % 3][b] = xs[2 + r0 + j + 3][w + b];
#pragma unroll
            for (int b = 0; b < 3; b++) V[j % 7][b] = xs[r0 + j + 7][2 + w + b];
        }
    }

#pragma unroll
    for (int off = 16; off; off >>= 1) lsum += __shfl_down_sync(0xffffffffu, lsum, off);
    if ((tid & 31) == 0) red[tid >> 5] = lsum;
    __syncthreads();
    if (tid == 0) {
        float s = 0.f;
#pragma unroll
        for (int i = 0; i < 7; i++) s += red[i];
        g_att[n * 128 + c] = s * (1.0f / HWc);
    }
}

// ---------------------------------------------------------------------------
// Tiny attention MLP (unchanged).
// ---------------------------------------------------------------------------
__global__ __launch_bounds__(128)
void att_k(const float* __restrict__ w1, const float* __restrict__ b1,
           const float* __restrict__ w2, const float* __restrict__ b2)
{
    __shared__ float satt[128];
    __shared__ float shid[64];
    const int n = blockIdx.x, tid = threadIdx.x;
    satt[tid] = g_att[n * 128 + tid];
    __syncthreads();
    if (tid < 64) {
        float acc = b1[tid];
        for (int c = 0; c < 128; c++) acc += satt[c] * w1[tid * 128 + c];
        shid[tid] = gelu_f(acc);
    }
    __syncthreads();
    float v[3];
#pragma unroll
    for (int k = 0; k < 3; k++) {
        float acc = b2[tid * 3 + k];
        for (int h = 0; h < 64; h++) acc += shid[h] * w2[(tid * 3 + k) * 64 + h];
        v[k] = acc;
    }
    const float m = fmaxf(v[0], fmaxf(v[1], v[2]));
    const float e0 = expf(v[0] - m), e1 = expf(v[1] - m), e2 = expf(v[2] - m);
    const float s = e0 + e1 + e2;
    g_a[n * 384 + tid * 3 + 0] = e0 / s;
    g_a[n * 384 + tid * 3 + 1] = e1 / s;
    g_a[n * 384 + tid * 3 + 2] = e2 / s;
}

// ---------------------------------------------------------------------------
extern "C" void kernel_launch(void* const* d_in, const int* in_sizes, int n_in,
                              void* d_out, int out_size)
{
    const float* x      = (const float*)d_in[0];
    const float* mlp_w  = (const float*)d_in[1];
    const float* mlp_b  = (const float*)d_in[2];
    const float* bn1_g  = (const float*)d_in[3];
    const float* bn1_b  = (const float*)d_in[4];
    const float* bn1_m  = (const float*)d_in[5];
    const float* bn1_v  = (const float*)d_in[6];
    const float* pos_h  = (const float*)d_in[7];
    const float* pos_w  = (const float*)d_in[8];
    const float* pjh_w  = (const float*)d_in[9];
    const float* pjh_b  = (const float*)d_in[10];
    const float* pjw_w  = (const float*)d_in[11];
    const float* pjw_b  = (const float*)d_in[12];
    const float* fuse_h = (const float*)d_in[13];
    const float* bn2_g  = (const float*)d_in[14];
    const float* bn2_b  = (const float*)d_in[15];
    const float* bn2_m  = (const float*)d_in[16];
    const float* bn2_v  = (const float*)d_in[17];
    const float* fuse_w = (const float*)d_in[18];
    const float* fch_w  = (const float*)d_in[19];
    const float* fcw_w  = (const float*)d_in[20];
    const float* rw_w1  = (const float*)d_in[21];
    const float* rw_b1  = (const float*)d_in[22];
    const float* rw_w2  = (const float*)d_in[23];
    const float* rw_b2  = (const float*)d_in[24];
    const float* fout_w = (const float*)d_in[25];

    float *yp, *catp, *t1p, *u1p, *x2hp, *x2wp, *ap;
    cudaGetSymbolAddress((void**)&yp,   g_y);
    cudaGetSymbolAddress((void**)&catp, g_cat);
    cudaGetSymbolAddress((void**)&t1p,  g_t1);
    cudaGetSymbolAddress((void**)&u1p,  g_u1);
    cudaGetSymbolAddress((void**)&x2hp, g_x2h);
    cudaGetSymbolAddress((void**)&x2wp, g_x2w);
    cudaGetSymbolAddress((void**)&ap,   g_a);

    const int sFull = Cc * HWc;
    const int sHalf = C1c * HWc;

    cudaFuncSetAttribute(tc_gemm<0,false>, cudaFuncAttributeMaxDynamicSharedMemorySize, SMEM_GEMM);
    cudaFuncSetAttribute(tc_gemm<1,false>, cudaFuncAttributeMaxDynamicSharedMemorySize, SMEM_GEMM);
    cudaFuncSetAttribute(tc_gemm<2,false>, cudaFuncAttributeMaxDynamicSharedMemorySize, SMEM_GEMM);
    cudaFuncSetAttribute(tc_gemm<0,true>,  cudaFuncAttributeMaxDynamicSharedMemorySize, SMEM_GEMM);

    // GEMM1: y = gelu(bn(x@mlp_w + mlp_b)) ; ch<128 += pos_h
    tc_gemm<1,false><<<dim3(Pc / 128, 2), 256, SMEM_GEMM>>>(mlp_w, x, 256, sFull, x, sFull,
        yp, sFull, mlp_b, bn1_g, bn1_b, bn1_m, bn1_v, pos_h,
        nullptr, nullptr, nullptr, 0, nullptr);

    // strip convs + depthwise + attention
    strip_k<false><<<dim3(64, 16), 224>>>(pjh_w, pjh_b);
    strip_k<true ><<<dim3(64, 16), 224>>>(pjw_w, pjw_b);
    dw_k<<<dim3(128, 16), 224>>>(fch_w, fcw_w);
    att_k<<<16, 128>>>(rw_w1, rw_b1, rw_w2, rw_b2);

    // GEMM2: t1 = gelu(bn(concat[cat, x1]@fuse_h)) + pos_w
    tc_gemm<2,false><<<dim3(Pc / 128, 1), 256, SMEM_GEMM>>>(fuse_h, catp, 128, sHalf, yp, sFull,
        t1p, sHalf, nullptr, bn2_g, bn2_b, bn2_m, bn2_v, pos_w,
        nullptr, nullptr, nullptr, 0, nullptr);

    // GEMM3: u1 = concat[t1, x2]@fuse_w
    tc_gemm<0,false><<<dim3(Pc / 128, 1), 256, SMEM_GEMM>>>(fuse_w, t1p, 128, sHalf, yp + 128 * HWc, sFull,
        u1p, sHalf, nullptr, nullptr, nullptr, nullptr, nullptr, nullptr,
        nullptr, nullptr, nullptr, 0, nullptr);

    // GEMM4: out = concat[u1, a0*x2h + a1*x2w + a2*x2]@fuse_out  (comb fused)
    tc_gemm<0,true><<<dim3(Pc / 128, 2), 256, SMEM_GEMM>>>(fout_w, u1p, 128, sHalf, nullptr, 0,
        (float*)d_out, sFull, nullptr, nullptr, nullptr, nullptr, nullptr, nullptr,
        x2hp, x2wp, yp + 128 * HWc, sFull, ap);
}

// round 6
// speedup vs baseline: 1.4673x; 1.1696x over previous
#include <cuda_runtime.h>
#include <cuda_bf16.h>
#include <math.h>
#include <stdint.h>

#define Nn   16
#define Cc   256
#define C1c  128
#define HWc  3136
#define EPSf 1e-5f
#define PBI  25          // pixel blocks per image (25*128 >= 3136)
#define NPB  (Nn*PBI)    // 400

// ---------------- scratch (device globals; no allocations) ----------------
__device__ float g_y  [Nn*Cc *HWc];
__device__ float g_x2h[Nn*C1c*HWc];
__device__ float g_x2w[Nn*C1c*HWc];
__device__ float g_att[Nn*C1c];
__device__ float g_a  [Nn*C1c*3];

// bf16 hi/lo activation buffers (uint4-typed for 16B alignment), +256 elem pad
__device__ uint4 g_ybh4[(Nn*Cc *HWc + 256) / 8];
__device__ uint4 g_ybl4[(Nn*Cc *HWc + 256) / 8];
__device__ uint4 g_cbh4[(Nn*C1c*HWc + 256) / 8];
__device__ uint4 g_cbl4[(Nn*C1c*HWc + 256) / 8];
__device__ uint4 g_t1h4[(Nn*C1c*HWc + 256) / 8];
__device__ uint4 g_t1l4[(Nn*C1c*HWc + 256) / 8];
__device__ uint4 g_u1h4[(Nn*C1c*HWc + 256) / 8];
__device__ uint4 g_u1l4[(Nn*C1c*HWc + 256) / 8];
// prepped weights: 6 o-block slots x 8 chunks x [128 n][40 halves]
__device__ uint4 g_wbh4[6 * 40960 / 8];
__device__ uint4 g_wbl4[6 * 40960 / 8];

__device__ __forceinline__ float gelu_f(float x) {
    return 0.5f * x * (1.0f + erff(x * 0.7071067811865476f));
}
__device__ __forceinline__ uint32_t smem_to_u32(const void* p) {
    uint32_t a;
    asm("{ .reg .u64 t; cvta.to.shared.u64 t, %1; cvt.u32.u64 %0, t; }" : "=r"(a) : "l"(p));
    return a;
}
__device__ __forceinline__ void split_bf2(float x0, float x1, uint32_t& hi, uint32_t& lo) {
    const __nv_bfloat16 h0 = __float2bfloat16(x0);
    const __nv_bfloat16 h1 = __float2bfloat16(x1);
    const float r0 = x0 - __bfloat162float(h0);
    const float r1 = x1 - __bfloat162float(h1);
    const __nv_bfloat16 l0 = __float2bfloat16(r0);
    const __nv_bfloat16 l1 = __float2bfloat16(r1);
    hi = (uint32_t)__bfloat16_as_ushort(h0) | ((uint32_t)__bfloat16_as_ushort(h1) << 16);
    lo = (uint32_t)__bfloat16_as_ushort(l0) | ((uint32_t)__bfloat16_as_ushort(l1) << 16);
}
__device__ __forceinline__ void ldsm4(uint32_t (&r)[4], uint32_t addr) {
    asm volatile("ldmatrix.sync.aligned.m8n8.x4.shared.b16 {%0,%1,%2,%3}, [%4];"
        : "=r"(r[0]), "=r"(r[1]), "=r"(r[2]), "=r"(r[3]) : "r"(addr));
}
__device__ __forceinline__ void ldsm4t(uint32_t (&r)[4], uint32_t addr) {
    asm volatile("ldmatrix.sync.aligned.m8n8.x4.trans.shared.b16 {%0,%1,%2,%3}, [%4];"
        : "=r"(r[0]), "=r"(r[1]), "=r"(r[2]), "=r"(r[3]) : "r"(addr));
}
__device__ __forceinline__ void mma16816(float (&c)[4], const uint32_t (&a)[4], uint32_t b0, uint32_t b1) {
    asm volatile("mma.sync.aligned.m16n8k16.row.col.f32.bf16.bf16.f32 "
        "{%0,%1,%2,%3}, {%4,%5,%6,%7}, {%8,%9}, {%0,%1,%2,%3};"
        : "+f"(c[0]), "+f"(c[1]), "+f"(c[2]), "+f"(c[3])
        : "r"(a[0]), "r"(a[1]), "r"(a[2]), "r"(a[3]), "r"(b0), "r"(b1));
}
#define CP16(dst, src) asm volatile("cp.async.cg.shared.global [%0], [%1], 16;" :: "r"(dst), "l"(src))
#define CP_COMMIT()    asm volatile("cp.async.commit_group;" ::: "memory")

// ---------------------------------------------------------------------------
// Weight prep: split fp32 W rows into bf16 hi/lo, laid out per o-block slot as
// the exact smem image: [kc 8][n 128][40 halves] (32 K-halves + 8 pad).
// slots: 0,1 = mlp_w(o0=0,128); 2 = fuse_h; 3 = fuse_w; 4,5 = fuse_out(0,128)
// ---------------------------------------------------------------------------
__global__ __launch_bounds__(256)
void wprep_k(const float* __restrict__ mlp_w, const float* __restrict__ fuse_h,
             const float* __restrict__ fuse_w, const float* __restrict__ fout_w)
{
    const int slot = blockIdx.x, kc = blockIdx.y, tid = threadIdx.x;
    const float* W; int o0;
    switch (slot) {
        case 0: W = mlp_w;  o0 = 0;   break;
        case 1: W = mlp_w;  o0 = 128; break;
        case 2: W = fuse_h; o0 = 0;   break;
        case 3: W = fuse_w; o0 = 0;   break;
        case 4: W = fout_w; o0 = 0;   break;
        default:W = fout_w; o0 = 128; break;
    }
    const int n = tid >> 1;
    const int kh = (tid & 1) * 16;
    const float* src = W + (long)(o0 + n) * 256 + kc * 32 + kh;
    uint32_t hi[8], lo[8];
#pragma unroll
    for (int j = 0; j < 8; j++) {
        const float2 v = *reinterpret_cast<const float2*>(src + 2 * j);
        split_bf2(v.x, v.y, hi[j], lo[j]);
    }
    __nv_bfloat16* dh = (__nv_bfloat16*)g_wbh4 + (long)slot * 40960 + kc * 5120 + n * 40 + kh;
    __nv_bfloat16* dl = (__nv_bfloat16*)g_wbl4 + (long)slot * 40960 + kc * 5120 + n * 40 + kh;
    *reinterpret_cast<uint4*>(dh)     = *reinterpret_cast<uint4*>(&hi[0]);
    *reinterpret_cast<uint4*>(dh + 8) = *reinterpret_cast<uint4*>(&hi[4]);
    *reinterpret_cast<uint4*>(dl)     = *reinterpret_cast<uint4*>(&lo[0]);
    *reinterpret_cast<uint4*>(dl + 8) = *reinterpret_cast<uint4*>(&lo[4]);
    if (tid < 128) {
        const uint4 z = {0, 0, 0, 0};
        *reinterpret_cast<uint4*>((__nv_bfloat16*)g_wbh4 + (long)slot * 40960 + kc * 5120 + tid * 40 + 32) = z;
        *reinterpret_cast<uint4*>((__nv_bfloat16*)g_wbl4 + (long)slot * 40960 + kc * 5120 + tid * 40 + 32) = z;
    }
}

// ---------------------------------------------------------------------------
// Tensor-core GEMM, K=256 in 8 chunks of 32, double-buffered cp.async pipeline.
// Block: 128 pixels (one image, pb*128..) x 128 out-ch. 8 warps (4m x 2n).
// smem per stage: Ah(8704) Al(8704) Bh(10240) Bl(10240) = 37888; x2 = 75776.
// APATH: 0 = bf16 cp.async (src1 ch<128, src2 else); 1 = fp32 convert (x);
//        2 = chunks 0-3 bf16 src1 (u1), chunks 4-7 fp32 comb a0*H+a1*W+a2*X.
// EPI: 0 none; 1 +bias,BN,gelu,+pos(o<128); 2 BN,gelu,+pos
// OUT: 0 fp32 only; 1 fp32 + bf16; 2 bf16 only
// ---------------------------------------------------------------------------
#define STG 37888
#define ALB 8704
#define BHB 17408
#define BLB 27648
#define SMEM_GEMM 75776

template<int APATH, int EPI, int OUT>
__global__ __launch_bounds__(256, 2)
void tc_gemm(const __nv_bfloat16* __restrict__ wbh, const __nv_bfloat16* __restrict__ wbl,
             const __nv_bfloat16* __restrict__ s1h, const __nv_bfloat16* __restrict__ s1l, int str1,
             const __nv_bfloat16* __restrict__ s2h, const __nv_bfloat16* __restrict__ s2l, int str2,
             const float* __restrict__ xin, int strX,
             float* __restrict__ out, int strO,
             __nv_bfloat16* __restrict__ obh, __nv_bfloat16* __restrict__ obl, int strOB,
             const float* __restrict__ e_bias,
             const float* __restrict__ e_g, const float* __restrict__ e_b,
             const float* __restrict__ e_m, const float* __restrict__ e_v,
             const float* __restrict__ e_pos,
             const float* __restrict__ cH, const float* __restrict__ cW,
             const float* __restrict__ cA)
{
    extern __shared__ __align__(16) char smc[];
    const uint32_t sm_sa = smem_to_u32(smc);

    const int tid = threadIdx.x;
    const int wid = tid >> 5;
    const int lane = tid & 31;
    const int o0 = blockIdx.x * 128;
    const int nimg = blockIdx.y / PBI;
    const int pix0 = (blockIdx.y % PBI) * 128;
    const int warp_m = (wid & 3) * 32;
    const int warp_n = (wid >> 2) * 64;

    const __nv_bfloat16* wbhB = wbh + (long)blockIdx.x * 40960;
    const __nv_bfloat16* wblB = wbl + (long)blockIdx.x * 40960;

    // register-path A geometry
    const int pix2 = tid & 63;
    const int rgrp = tid >> 6;
    int p0 = pix0 + 2 * pix2;
    if (p0 > HWc - 2) p0 = HWc - 2;

    auto issue = [&](int kc, int buf) {
        const uint32_t base = sm_sa + buf * STG;
        char* bp = smc + buf * STG;
        // ---- A ----
        if (APATH == 1) {
            const float* src = xin + (long)nimg * strX + p0;
#pragma unroll
            for (int j = 0; j < 8; j++) {
                const int r = rgrp + 4 * j;
                const float2 v = *reinterpret_cast<const float2*>(src + (long)(kc * 32 + r) * HWc);
                uint32_t hi, lo;
                split_bf2(v.x, v.y, hi, lo);
                *reinterpret_cast<uint32_t*>(bp + r * 272 + pix2 * 4) = hi;
                *reinterpret_cast<uint32_t*>(bp + ALB + r * 272 + pix2 * 4) = lo;
            }
        } else if (APATH == 0 || kc < 4) {
            const int c0 = kc * 32;
            const __nv_bfloat16 *sh, *sl;
            long chb;
            if (c0 < 128) { sh = s1h; sl = s1l; chb = (long)nimg * str1 + (long)c0 * HWc + pix0; }
            else          { sh = s2h; sl = s2l; chb = (long)nimg * str2 + (long)(c0 - 128) * HWc + pix0; }
#pragma unroll
            for (int it = 0; it < 2; it++) {
                const int idx = tid + it * 256;
                const int row = idx >> 4, seg = idx & 15;
                const char* gh = (const char*)(sh + chb + (long)row * HWc) + seg * 16;
                const char* gl = (const char*)(sl + chb + (long)row * HWc) + seg * 16;
                CP16(base + row * 272 + seg * 16, gh);
                CP16(base + ALB + row * 272 + seg * 16, gl);
            }
        } else {
            // APATH 2, kc >= 4: comb = a0*x2h + a1*x2w + a2*x2
            const long ib = (long)nimg * (C1c * HWc) + p0;
            const float* pH = cH + ib;
            const float* pW = cW + ib;
            const float* pX = xin + (long)nimg * strX + (long)128 * HWc + p0;
            const float* aB = cA + nimg * 384;
#pragma unroll
            for (int j = 0; j < 8; j++) {
                const int r = rgrp + 4 * j;
                const int cc = (kc - 4) * 32 + r;
                const float a0 = aB[cc * 3], a1 = aB[cc * 3 + 1], a2 = aB[cc * 3 + 2];
                const float2 vh = *reinterpret_cast<const float2*>(pH + (long)cc * HWc);
                const float2 vw = *reinterpret_cast<const float2*>(pW + (long)cc * HWc);
                const float2 vx = *reinterpret_cast<const float2*>(pX + (long)cc * HWc);
                float2 v;
                v.x = a0 * vh.x + a1 * vw.x + a2 * vx.x;
                v.y = a0 * vh.y + a1 * vw.y + a2 * vx.y;
                uint32_t hi, lo;
                split_bf2(v.x, v.y, hi, lo);
                *reinterpret_cast<uint32_t*>(bp + r * 272 + pix2 * 4) = hi;
                *reinterpret_cast<uint32_t*>(bp + ALB + r * 272 + pix2 * 4) = lo;
            }
        }
        // ---- B: linear copy of prepped chunk image (10240B each) ----
        const char* wh = (const char*)(wbhB + kc * 5120);
        const char* wl = (const char*)(wblB + kc * 5120);
#pragma unroll
        for (int it = 0; it < 3; it++) {
            const int i = tid + it * 256;
            if (i < 640) {
                CP16(base + BHB + i * 16, wh + i * 16);
                CP16(base + BLB + i * 16, wl + i * 16);
            }
        }
    };

    // ldmatrix lane geometry
    const int a_kr = (lane & 7) + ((lane & 16) >> 1);
    const int a_mc = (lane & 8);
    const int b_nr = (lane & 7) + ((lane & 16) >> 1);
    const int b_kc = (lane & 8);

    float acc[2][8][4];
#pragma unroll
    for (int mt = 0; mt < 2; mt++)
#pragma unroll
        for (int nf = 0; nf < 8; nf++)
#pragma unroll
            for (int j = 0; j < 4; j++) acc[mt][nf][j] = 0.f;

    issue(0, 0);
    CP_COMMIT();

#pragma unroll 1
    for (int kc = 0; kc < 8; kc++) {
        if (kc < 7) { issue(kc + 1, (kc + 1) & 1); CP_COMMIT(); }
        if (kc < 7) asm volatile("cp.async.wait_group 1;" ::: "memory");
        else        asm volatile("cp.async.wait_group 0;" ::: "memory");
        __syncthreads();

        const uint32_t base = sm_sa + (kc & 1) * STG;
#pragma unroll
        for (int ks = 0; ks < 2; ks++) {
            const int k0 = ks * 16;
            uint32_t ah[2][4], al[2][4];
#pragma unroll
            for (int half = 0; half < 2; half++) {
                const uint32_t ea = (uint32_t)((k0 + a_kr) * 136 + warp_m + half * 16 + a_mc) * 2;
                ldsm4t(ah[half], base + ea);
                ldsm4t(al[half], base + ALB + ea);
            }
#pragma unroll
            for (int ng = 0; ng < 4; ng++) {
                const uint32_t eb = (uint32_t)((warp_n + ng * 16 + b_nr) * 40 + k0 + b_kc) * 2;
                uint32_t th[4], tl[4];
                ldsm4(th, base + BHB + eb);
                ldsm4(tl, base + BLB + eb);
#pragma unroll
                for (int mt = 0; mt < 2; mt++) {
                    mma16816(acc[mt][2 * ng],     ah[mt], th[0], th[1]);
                    mma16816(acc[mt][2 * ng],     al[mt], th[0], th[1]);
                    mma16816(acc[mt][2 * ng],     ah[mt], tl[0], tl[1]);
                    mma16816(acc[mt][2 * ng + 1], ah[mt], th[2], th[3]);
                    mma16816(acc[mt][2 * ng + 1], al[mt], th[2], th[3]);
                    mma16816(acc[mt][2 * ng + 1], ah[mt], tl[2], tl[3]);
                }
            }
        }
        __syncthreads();
    }

    // ---- epilogue: transpose through smem, coalesced stores, pixel guards ----
    float* O = reinterpret_cast<float*>(smc);   // [128 n][132 m]
#pragma unroll
    for (int mt = 0; mt < 2; mt++)
#pragma unroll
        for (int nf = 0; nf < 8; nf++) {
            const int n = warp_n + nf * 8 + (lane & 3) * 2;
            const int m = warp_m + mt * 16 + (lane >> 2);
            O[n * 132 + m]           = acc[mt][nf][0];
            O[(n + 1) * 132 + m]     = acc[mt][nf][1];
            O[n * 132 + m + 8]       = acc[mt][nf][2];
            O[(n + 1) * 132 + m + 8] = acc[mt][nf][3];
        }
    __syncthreads();

    {
        const int m0 = lane * 4;
        const int hw0 = pix0 + m0;
        const bool pvalid = (hw0 < HWc);
        int rel[4] = {0, 0, 0, 0};
        if (pvalid && EPI != 0) {
#pragma unroll
            for (int j = 0; j < 4; j++) {
                const int hwj = hw0 + j;
                const int h = hwj / 56;
                rel[j] = (hwj - h * 56) - h + 56;
            }
        }
        if (pvalid) {
#pragma unroll
            for (int r = 0; r < 16; r++) {
                const int n = wid * 16 + r;
                const int o = o0 + n;
                const float4 v = *reinterpret_cast<const float4*>(&O[n * 132 + m0]);
                float vv[4] = {v.x, v.y, v.z, v.w};
                if (EPI == 1) {
                    const float s = __ldg(&e_g[o]) * rsqrtf(__ldg(&e_v[o]) + EPSf);
                    const float t = __ldg(&e_b[o]) - __ldg(&e_m[o]) * s;
                    const float bb = __ldg(&e_bias[o]);
#pragma unroll
                    for (int j = 0; j < 4; j++) {
                        float u = gelu_f((vv[j] + bb) * s + t);
                        if (o < 128) u += __ldg(&e_pos[rel[j] * 128 + o]);
                        vv[j] = u;
                    }
                } else if (EPI == 2) {
                    const float s = __ldg(&e_g[o]) * rsqrtf(__ldg(&e_v[o]) + EPSf);
                    const float t = __ldg(&e_b[o]) - __ldg(&e_m[o]) * s;
#pragma unroll
                    for (int j = 0; j < 4; j++)
                        vv[j] = gelu_f(vv[j] * s + t) + __ldg(&e_pos[rel[j] * 128 + o]);
                }
                if (OUT != 2) {
                    float4 ov;
                    ov.x = vv[0]; ov.y = vv[1]; ov.z = vv[2]; ov.w = vv[3];
                    *reinterpret_cast<float4*>(&out[(long)nimg * strO + (long)o * HWc + hw0]) = ov;
                }
                if (OUT != 0) {
                    uint32_t h0, l0, h1, l1;
                    split_bf2(vv[0], vv[1], h0, l0);
                    split_bf2(vv[2], vv[3], h1, l1);
                    const long eoff = (long)nimg * strOB + (long)o * HWc + hw0;
                    *reinterpret_cast<uint2*>(obh + eoff) = make_uint2(h0, h1);
                    *reinterpret_cast<uint2*>(obl + eoff) = make_uint2(l0, l1);
                }
            }
        }
    }
}

// ---------------------------------------------------------------------------
// Strip conv -> bf16 hi/lo output into g_cbf (channels 0..63 H-var, 64..127 W-var)
// ---------------------------------------------------------------------------
template<bool WVAR>
__global__ __launch_bounds__(224)
void strip_k(const float* __restrict__ Wg, const float* __restrict__ bias)
{
    __shared__ float xs[58][58];
    __shared__ float os[3136];
    const int c = blockIdx.x, n = blockIdx.y;
    const int tid = threadIdx.x;

    for (int i = tid; i < 58 * 58; i += 224) ((float*)xs)[i] = 0.f;
    __syncthreads();
    const float* src = g_y + (long)n * Cc * HWc + (long)((WVAR ? 64 : 0) + c) * HWc;
    for (int i = tid; i < HWc; i += 224) {
        const int h = i / 56;
        xs[1 + h][1 + (i - h * 56)] = src[i];
    }
    __syncthreads();

    const int oo = tid >> 2;
    const int base0 = (tid & 3) * 14;
    const float* wrow = Wg + ((long)c * 56 + oo) * 168;

    float acc[14];
    const float bval = __ldg(&bias[c * 56 + oo]);
#pragma unroll
    for (int i = 0; i < 14; i++) acc[i] = bval;

    __nv_bfloat16* cbh = (__nv_bfloat16*)g_cbh4;
    __nv_bfloat16* cbl = (__nv_bfloat16*)g_cbl4;

    if (!WVAR) {
        for (int hp = 0; hp < 56; hp++) {
            const float w0 = __ldg(&wrow[hp * 3 + 0]);
            const float w1 = __ldg(&wrow[hp * 3 + 1]);
            const float w2 = __ldg(&wrow[hp * 3 + 2]);
            float xv[16];
#pragma unroll
            for (int t = 0; t < 16; t++) xv[t] = xs[1 + hp][base0 + t];
#pragma unroll
            for (int i = 0; i < 14; i++) acc[i] += w0 * xv[i] + w1 * xv[i + 1] + w2 * xv[i + 2];
        }
        const long dst = (long)n * C1c * HWc + (long)c * HWc + oo * 56 + base0;
#pragma unroll
        for (int i = 0; i < 7; i++) {
            uint32_t hi, lo;
            split_bf2(acc[2 * i], acc[2 * i + 1], hi, lo);
            *reinterpret_cast<uint32_t*>(cbh + dst + 2 * i) = hi;
            *reinterpret_cast<uint32_t*>(cbl + dst + 2 * i) = lo;
        }
    } else {
        for (int wp = 0; wp < 56; wp++) {
            const float w0 = __ldg(&wrow[wp * 3 + 0]);
            const float w1 = __ldg(&wrow[wp * 3 + 1]);
            const float w2 = __ldg(&wrow[wp * 3 + 2]);
            float xv[16];
#pragma unroll
            for (int t = 0; t < 16; t++) xv[t] = xs[base0 + t][1 + wp];
#pragma unroll
            for (int i = 0; i < 14; i++) acc[i] += w0 * xv[i] + w1 * xv[i + 1] + w2 * xv[i + 2];
        }
#pragma unroll
        for (int i = 0; i < 14; i++) os[(base0 + i) * 56 + oo] = acc[i];
        __syncthreads();
        const int p0 = tid * 14;
        const long dst = (long)n * C1c * HWc + (long)(64 + c) * HWc + p0;
#pragma unroll
        for (int i = 0; i < 7; i++) {
            uint32_t hi, lo;
            split_bf2(os[p0 + 2 * i], os[p0 + 2 * i + 1], hi, lo);
            *reinterpret_cast<uint32_t*>(cbh + dst + 2 * i) = hi;
            *reinterpret_cast<uint32_t*>(cbl + dst + 2 * i) = lo;
        }
    }
}

// ---------------------------------------------------------------------------
// Depthwise 3x7 + 7x3 + channel mean (register-sliding, unchanged from R5).
// ---------------------------------------------------------------------------
__global__ __launch_bounds__(224)
void dw_k(const float* __restrict__ wh, const float* __restrict__ ww)
{
    __shared__ float xs[62][62];
    __shared__ float red[7];
    const int c = blockIdx.x, n = blockIdx.y;
    const int tid = threadIdx.x;

    for (int i = tid; i < 62 * 62; i += 224) ((float*)xs)[i] = 0.f;
    __syncthreads();
    const float* src = g_y + (long)n * Cc * HWc + (long)(128 + c) * HWc;
    for (int i = tid; i < HWc; i += 224) {
        const int h = i / 56;
        xs[3 + h][3 + (i - h * 56)] = src[i];
    }
    __syncthreads();

    float kh_[21], kw_[21];
#pragma unroll
    for (int i = 0; i < 21; i++) { kh_[i] = __ldg(&wh[c * 21 + i]); kw_[i] = __ldg(&ww[c * 21 + i]); }

    const int w = tid % 56;
    const int r0 = (tid / 56) * 14;

    float R[3][7], V[7][3];
#pragma unroll
    for (int a = 0; a < 3; a++)
#pragma unroll
        for (int b = 0; b < 7; b++) R[a][b] = xs[2 + r0 + a][w + b];
#pragma unroll
    for (int a = 0; a < 7; a++)
#pragma unroll
        for (int b = 0; b < 3; b++) V[a][b] = xs[r0 + a][2 + w + b];

    float lsum = 0.f;
    float* dh = g_x2h + (long)n * C1c * HWc + (long)c * HWc + w;
    float* dv = g_x2w + (long)n * C1c * HWc + (long)c * HWc + w;

#pragma unroll
    for (int j = 0; j < 14; j++) {
        float vh = 0.f, vw = 0.f;
#pragma unroll
        for (int a = 0; a < 3; a++)
#pragma unroll
            for (int b = 0; b < 7; b++)
                vh += kh_[a * 7 + b] * R[(j + a) % 3][b];
#pragma unroll
        for (int a = 0; a < 7; a++)
#pragma unroll
            for (int b = 0; b < 3; b++)
                vw += kw_[a * 3 + b] * V[(j + a) % 7][b];
        const float cen = R[(j + 1) % 3][3];
        dh[(r0 + j) * 56] = vh;
        dv[(r0 + j) * 56] = vw;
        lsum += vh + vw + cen;
        if (j < 13) {
#pragma unroll
            for (int b = 0; b < 7; b++) R[j % 3][b] = xs[2 + r0 + j + 3][w + b];
#pragma unroll
            for (int b = 0; b < 3; b++) V[j % 7][b] = xs[r0 + j + 7][2 + w + b];
        }
    }

#pragma unroll
    for (int off = 16; off; off >>= 1) lsum += __shfl_down_sync(0xffffffffu, lsum, off);
    if ((tid & 31) == 0) red[tid >> 5] = lsum;
    __syncthreads();
    if (tid == 0) {
        float s = 0.f;
#pragma unroll
        for (int i = 0; i < 7; i++) s += red[i];
        g_att[n * 128 + c] = s * (1.0f / HWc);
    }
}

// ---------------------------------------------------------------------------
// Tiny attention MLP (unchanged).
// ---------------------------------------------------------------------------
__global__ __launch_bounds__(128)
void att_k(const float* __restrict__ w1, const float* __restrict__ b1,
           const float* __restrict__ w2, const float* __restrict__ b2)
{
    __shared__ float satt[128];
    __shared__ float shid[64];
    const int n = blockIdx.x, tid = threadIdx.x;
    satt[tid] = g_att[n * 128 + tid];
    __syncthreads();
    if (tid < 64) {
        float acc = b1[tid];
        for (int c = 0; c < 128; c++) acc += satt[c] * w1[tid * 128 + c];
        shid[tid] = gelu_f(acc);
    }
    __syncthreads();
    float v[3];
#pragma unroll
    for (int k = 0; k < 3; k++) {
        float acc = b2[tid * 3 + k];
        for (int h = 0; h < 64; h++) acc += shid[h] * w2[(tid * 3 + k) * 64 + h];
        v[k] = acc;
    }
    const float m = fmaxf(v[0], fmaxf(v[1], v[2]));
    const float e0 = expf(v[0] - m), e1 = expf(v[1] - m), e2 = expf(v[2] - m);
    const float s = e0 + e1 + e2;
    g_a[n * 384 + tid * 3 + 0] = e0 / s;
    g_a[n * 384 + tid * 3 + 1] = e1 / s;
    g_a[n * 384 + tid * 3 + 2] = e2 / s;
}

// ---------------------------------------------------------------------------
extern "C" void kernel_launch(void* const* d_in, const int* in_sizes, int n_in,
                              void* d_out, int out_size)
{
    const float* x      = (const float*)d_in[0];
    const float* mlp_w  = (const float*)d_in[1];
    const float* mlp_b  = (const float*)d_in[2];
    const float* bn1_g  = (const float*)d_in[3];
    const float* bn1_b  = (const float*)d_in[4];
    const float* bn1_m  = (const float*)d_in[5];
    const float* bn1_v  = (const float*)d_in[6];
    const float* pos_h  = (const float*)d_in[7];
    const float* pos_w  = (const float*)d_in[8];
    const float* pjh_w  = (const float*)d_in[9];
    const float* pjh_b  = (const float*)d_in[10];
    const float* pjw_w  = (const float*)d_in[11];
    const float* pjw_b  = (const float*)d_in[12];
    const float* fuse_h = (const float*)d_in[13];
    const float* bn2_g  = (const float*)d_in[14];
    const float* bn2_b  = (const float*)d_in[15];
    const float* bn2_m  = (const float*)d_in[16];
    const float* bn2_v  = (const float*)d_in[17];
    const float* fuse_w = (const float*)d_in[18];
    const float* fch_w  = (const float*)d_in[19];
    const float* fcw_w  = (const float*)d_in[20];
    const float* rw_w1  = (const float*)d_in[21];
    const float* rw_b1  = (const float*)d_in[22];
    const float* rw_w2  = (const float*)d_in[23];
    const float* rw_b2  = (const float*)d_in[24];
    const float* fout_w = (const float*)d_in[25];

    float *yp, *x2hp, *x2wp, *ap;
    void *ybh, *ybl, *cbh, *cbl, *t1h, *t1l, *u1h, *u1l, *wbh, *wbl;
    cudaGetSymbolAddress((void**)&yp,   g_y);
    cudaGetSymbolAddress((void**)&x2hp, g_x2h);
    cudaGetSymbolAddress((void**)&x2wp, g_x2w);
    cudaGetSymbolAddress((void**)&ap,   g_a);
    cudaGetSymbolAddress(&ybh, g_ybh4);
    cudaGetSymbolAddress(&ybl, g_ybl4);
    cudaGetSymbolAddress(&cbh, g_cbh4);
    cudaGetSymbolAddress(&cbl, g_cbl4);
    cudaGetSymbolAddress(&t1h, g_t1h4);
    cudaGetSymbolAddress(&t1l, g_t1l4);
    cudaGetSymbolAddress(&u1h, g_u1h4);
    cudaGetSymbolAddress(&u1l, g_u1l4);
    cudaGetSymbolAddress(&wbh, g_wbh4);
    cudaGetSymbolAddress(&wbl, g_wbl4);

    const __nv_bfloat16* WBH = (const __nv_bfloat16*)wbh;
    const __nv_bfloat16* WBL = (const __nv_bfloat16*)wbl;
    const int sFull = Cc * HWc;
    const int sHalf = C1c * HWc;

    cudaFuncSetAttribute(tc_gemm<1,1,1>, cudaFuncAttributeMaxDynamicSharedMemorySize, SMEM_GEMM);
    cudaFuncSetAttribute(tc_gemm<0,2,2>, cudaFuncAttributeMaxDynamicSharedMemorySize, SMEM_GEMM);
    cudaFuncSetAttribute(tc_gemm<0,0,2>, cudaFuncAttributeMaxDynamicSharedMemorySize, SMEM_GEMM);
    cudaFuncSetAttribute(tc_gemm<2,0,0>, cudaFuncAttributeMaxDynamicSharedMemorySize, SMEM_GEMM);

    // weight prep (slots 0-5)
    wprep_k<<<dim3(6, 8), 256>>>(mlp_w, fuse_h, fuse_w, fout_w);

    // GEMM1: y = gelu(bn(x@mlp_w + b)), ch<128 += pos_h ; out fp32 + bf16
    tc_gemm<1,1,1><<<dim3(2, NPB), 256, SMEM_GEMM>>>(
        WBH, WBL, nullptr, nullptr, 0, nullptr, nullptr, 0,
        x, sFull, yp, sFull,
        (__nv_bfloat16*)ybh, (__nv_bfloat16*)ybl, sFull,
        mlp_b, bn1_g, bn1_b, bn1_m, bn1_v, pos_h, nullptr, nullptr, nullptr);

    strip_k<false><<<dim3(64, 16), 224>>>(pjh_w, pjh_b);
    strip_k<true ><<<dim3(64, 16), 224>>>(pjw_w, pjw_b);
    dw_k<<<dim3(128, 16), 224>>>(fch_w, fcw_w);
    att_k<<<16, 128>>>(rw_w1, rw_b1, rw_w2, rw_b2);

    // GEMM2: t1 = gelu(bn(concat[cat, y[:,0:128]]@fuse_h)) + pos_w ; bf16 only
    tc_gemm<0,2,2><<<dim3(1, NPB), 256, SMEM_GEMM>>>(
        WBH + 2L * 40960, WBL + 2L * 40960,
        (const __nv_bfloat16*)cbh, (const __nv_bfloat16*)cbl, sHalf,
        (const __nv_bfloat16*)ybh, (const __nv_bfloat16*)ybl, sFull,
        nullptr, 0, nullptr, 0,
        (__nv_bfloat16*)t1h, (__nv_bfloat16*)t1l, sHalf,
        nullptr, bn2_g, bn2_b, bn2_m, bn2_v, pos_w, nullptr, nullptr, nullptr);

    // GEMM3: u1 = concat[t1, y[:,128:256]]@fuse_w ; bf16 only
    tc_gemm<0,0,2><<<dim3(1, NPB), 256, SMEM_GEMM>>>(
        WBH + 3L * 40960, WBL + 3L * 40960,
        (const __nv_bfloat16*)t1h, (const __nv_bfloat16*)t1l, sHalf,
        (const __nv_bfloat16*)ybh + 128L * HWc, (const __nv_bfloat16*)ybl + 128L * HWc, sFull,
        nullptr, 0, nullptr, 0,
        (__nv_bfloat16*)u1h, (__nv_bfloat16*)u1l, sHalf,
        nullptr, nullptr, nullptr, nullptr, nullptr, nullptr, nullptr, nullptr, nullptr);

    // GEMM4: out = concat[u1, a0*x2h + a1*x2w + a2*x2]@fuse_out ; fp32 out
    tc_gemm<2,0,0><<<dim3(2, NPB), 256, SMEM_GEMM>>>(
        WBH + 4L * 40960, WBL + 4L * 40960,
        (const __nv_bfloat16*)u1h, (const __nv_bfloat16*)u1l, sHalf,
        nullptr, nullptr, 0,
        yp, sFull, (float*)d_out, sFull,
        nullptr, nullptr, 0,
        nullptr, nullptr, nullptr, nullptr, nullptr, nullptr,
        x2hp, x2wp, ap);
}